// round 4
// baseline (speedup 1.0000x reference)
#include <cuda_runtime.h>
#include <math.h>

#define Bn 4
#define Cn 32
#define On 32
#define MD 12
#define MHW 24

__device__ float2 g_X1[Bn*Cn*64*MD*64];
__device__ float2 g_X2[Bn*Cn*MHW*MD*64];
__device__ float2 g_X3[Bn*Cn*MD*MHW*MHW];
__device__ float2 g_Y [Bn*On*MD*MHW*MHW];
__device__ float2 g_Z1[Bn*On*64*MD*MHW];
__device__ float2 g_Z2[Bn*On*64*64*MD];
__device__ float  g_CFT[256*576];
__device__ float  g_CORR[Bn*On*64];

__device__ __forceinline__ double ffma2(double a, double b, double c) {
    unsigned long long r;
    asm("fma.rn.f32x2 %0, %1, %2, %3;" : "=l"(r)
        : "l"(__double_as_longlong(a)), "l"(__double_as_longlong(b)), "l"(__double_as_longlong(c)));
    return __longlong_as_double(r);
}
__device__ __forceinline__ double pk(float lo, float hi) {
    return __hiloint2double(__float_as_int(hi), __float_as_int(lo));
}
__device__ __forceinline__ float plo(double d) { return __int_as_float(__double2loint(d)); }
__device__ __forceinline__ float phi(double d) { return __int_as_float(__double2hiint(d)); }
__device__ __forceinline__ double ldb(const double* b, int off) {
    return *(const double*)((const char*)b + off);
}
__device__ __forceinline__ void initE(float2* E, int t, int nthr) {
    for (int i = t; i < 64; i += nthr)
        E[i] = make_float2(cospif(i * (1.0f/32.0f)), sinpif(i * (1.0f/32.0f)));
}

// F1: real DFT along D. grid 4096 (2 rows/block), 128 thr, dyn smem 66560
__global__ void __launch_bounds__(128) k_f1(const float* __restrict__ x) {
    extern __shared__ double sm1[];          // [2][64*65] dup pairs
    __shared__ double E2[64];                // (c,-s)
    int t = threadIdx.x;
    if (t < 64) E2[t] = pk(cospif(t*(1.0f/32.0f)), -sinpif(t*(1.0f/32.0f)));
    const float* xr = x + (size_t)blockIdx.x * 8192;
    for (int i = t; i < 8192; i += 128) {
        int hh = i >> 12, r = i & 4095;
        float v = xr[i];
        sm1[hh*4160 + (r>>6)*65 + (r&63)] = pk(v, v);
    }
    __syncthreads();
    int hh = t >> 6, jg = (t >> 4) & 3, wg = t & 15, kd0 = jg*3;
    const double* xrow = sm1 + hh*4160;
    double a0[4], a1[4], a2[4];
    #pragma unroll
    for (int j = 0; j < 4; j++) { a0[j]=0; a1[j]=0; a2[j]=0; }
    int i0=0, i1=0, i2=0, s0=kd0*8, s1=s0+8, s2=s0+16;
    #pragma unroll 8
    for (int d = 0; d < 64; d++) {
        double e0 = ldb(E2,i0), e1 = ldb(E2,i1), e2 = ldb(E2,i2);
        i0=(i0+s0)&511; i1=(i1+s1)&511; i2=(i2+s2)&511;
        #pragma unroll
        for (int j = 0; j < 4; j++) {
            double xv = xrow[(wg + j*16)*65 + d];
            a0[j]=ffma2(xv,e0,a0[j]); a1[j]=ffma2(xv,e1,a1[j]); a2[j]=ffma2(xv,e2,a2[j]);
        }
    }
    double* o = (double*)g_X1 + (size_t)(blockIdx.x*2 + hh) * 768;
    #pragma unroll
    for (int j = 0; j < 4; j++) {
        int w = wg + j*16;
        o[kd0*64+w]=a0[j]; o[(kd0+1)*64+w]=a1[j]; o[(kd0+2)*64+w]=a2[j];
    }
}

// F2: DFT along W. grid 1536=(bc,kd), 128 thr, dyn smem 66560
__global__ void __launch_bounds__(128) k_f2() {
    extern __shared__ double sm2[];          // A[64*65] [w][h], Asw same
    __shared__ double Exx[64], Eyy[64];
    int t = threadIdx.x;
    if (t < 64) {
        float c = cospif(t*(1.0f/32.0f)), s = sinpif(t*(1.0f/32.0f));
        Exx[t] = pk(c,c); Eyy[t] = pk(s,s);
    }
    int bc = blockIdx.x / 12, kd = blockIdx.x % 12;
    const double* src = (const double*)g_X1 + (size_t)bc*64*768 + kd*64;
    double* A = sm2; double* Asw = sm2 + 4160;
    for (int i = t; i < 4096; i += 128) {
        int h = i >> 6, w = i & 63;
        double a = src[(size_t)h*768 + w];
        int lo = __double2loint(a), hi = __double2hiint(a);
        A[w*65+h] = a;
        Asw[w*65+h] = __hiloint2double(lo ^ 0x80000000, hi);   // (a.y,-a.x)
    }
    __syncthreads();
    int hx = t & 31, kwg = t >> 5;
    double ac0[6], ac1[6]; int idx[6], stp[6];
    #pragma unroll
    for (int u = 0; u < 6; u++) {
        int kw = kwg*6+u;
        stp[u] = (kw + (kw>=12 ? 40 : 0))*8; idx[u]=0; ac0[u]=0; ac1[u]=0;
    }
    #pragma unroll 4
    for (int w = 0; w < 64; w++) {
        double av0=A[w*65+hx], av1=A[w*65+hx+32], sv0=Asw[w*65+hx], sv1=Asw[w*65+hx+32];
        #pragma unroll
        for (int u = 0; u < 6; u++) {
            double ex = ldb(Exx, idx[u]), ey = ldb(Eyy, idx[u]);
            idx[u] = (idx[u] + stp[u]) & 511;
            ac0[u]=ffma2(av0,ex,ac0[u]); ac0[u]=ffma2(sv0,ey,ac0[u]);
            ac1[u]=ffma2(av1,ex,ac1[u]); ac1[u]=ffma2(sv1,ey,ac1[u]);
        }
    }
    #pragma unroll
    for (int u = 0; u < 6; u++) {
        double* o = (double*)g_X2 + ((size_t)(bc*24 + kwg*6+u)*12 + kd)*64;
        o[hx]=ac0[u]; o[hx+32]=ac1[u];
    }
}

// F3: DFT along H. grid 1536, 288 thr (unchanged scalar)
__global__ void k_f3() {
    __shared__ float2 Bt[24*65];
    __shared__ float2 E[64];
    int t = threadIdx.x;
    initE(E, t, 288);
    int bc = blockIdx.x / 12, kd = blockIdx.x % 12;
    for (int i = t; i < 24*64; i += 288)
        Bt[(i>>6)*65 + (i&63)] = g_X2[((size_t)(bc*24 + (i>>6))*12 + kd)*64 + (i&63)];
    __syncthreads();
    int kw = t % 24, kh2 = t / 24;
    float r0=0,i0=0,r1=0,i1=0;
    for (int h = 0; h < 64; h++) {
        float2 a = Bt[kw*65+h];
        float2 e0 = E[(kh2*h)&63];
        float2 e1 = E[((kh2+52)*h)&63];
        r0 = fmaf(a.x,e0.x,fmaf( a.y,e0.y,r0));
        i0 = fmaf(a.y,e0.x,fmaf(-a.x,e0.y,i0));
        r1 = fmaf(a.x,e1.x,fmaf( a.y,e1.y,r1));
        i1 = fmaf(a.y,e1.x,fmaf(-a.x,e1.y,i1));
    }
    float2* o = g_X3 + (size_t)(bc*12 + kd)*576;
    o[kh2*24+kw] = make_float2(r0,i0);
    o[(kh2+12)*24+kw] = make_float2(r1,i1);
}

// MIX. grid 576, 128 thr, dyn smem 110592 (unchanged)
__global__ void k_mix(const float* __restrict__ w1re, const float* __restrict__ w1im,
                      const float* __restrict__ w2re, const float* __restrict__ w2im,
                      const float* __restrict__ w3re, const float* __restrict__ w3im,
                      const float* __restrict__ w4re, const float* __restrict__ w4im) {
    extern __shared__ float sm[];
    float*  Wre = sm;
    float*  Wim = sm + 12288;
    float2* X3s = (float2*)(sm + 24576);
    const float* wres[4] = {w1re, w2re, w3re, w4re};
    const float* wims[4] = {w1im, w2im, w3im, w4im};
    int t = threadIdx.x;
    int q = blockIdx.x / 144, mm = blockIdx.x % 144;
    int m1 = mm / 12, m2 = mm % 12;
    int mhw = (m1 + (q&1)*12)*24 + m2 + ((q>>1)&1)*12;
    const float* wre = wres[q];
    const float* wim = wims[q];
    for (int idx = t; idx < 12288; idx += 128) {
        int io = idx / 12, kd = idx % 12;
        size_t g = (size_t)io*1728 + m1*144 + m2*12 + kd;
        int sl = ((io>>5)*12 + kd)*32 + (io&31);
        Wre[sl] = wre[g]; Wim[sl] = wim[g];
    }
    for (int idx = t; idx < 1536; idx += 128)
        X3s[idx] = g_X3[(size_t)idx*576 + mhw];
    __syncthreads();
    int b = t >> 5, o = t & 31;
    float2 acc[12];
    #pragma unroll
    for (int kd = 0; kd < 12; kd++) acc[kd] = make_float2(0,0);
    for (int i = 0; i < 32; i++) {
        int xb = (b*32+i)*12, wb = i*384 + o;
        #pragma unroll
        for (int kd = 0; kd < 12; kd++) {
            float2 a = X3s[xb+kd];
            float wr = Wre[wb+kd*32], wi = Wim[wb+kd*32];
            acc[kd].x = fmaf(a.x,wr,fmaf(-a.y,wi,acc[kd].x));
            acc[kd].y = fmaf(a.x,wi,fmaf( a.y,wr,acc[kd].y));
        }
    }
    #pragma unroll
    for (int kd = 0; kd < 12; kd++)
        g_Y[((size_t)(b*32+o)*12+kd)*576 + mhw] = acc[kd];
}

// I1: inverse DFT along H. grid 1536, 256 thr (unchanged)
__global__ void k_i1() {
    __shared__ float2 Ys[576];
    __shared__ float2 E[64];
    int t = threadIdx.x;
    initE(E, t, 256);
    int bo = blockIdx.x / 12, kd = blockIdx.x % 12;
    for (int i = t; i < 576; i += 256)
        Ys[i] = g_Y[(size_t)(bo*12+kd)*576 + i];
    __syncthreads();
    int h = t & 63, kwg = t >> 6;
    float2 acc[6];
    #pragma unroll
    for (int u = 0; u < 6; u++) acc[u] = make_float2(0,0);
    for (int kh = 0; kh < 24; kh++) {
        float2 e = E[((kh + (kh>=12?40:0))*h)&63];
        #pragma unroll
        for (int u = 0; u < 6; u++) {
            float2 a = Ys[kh*24 + kwg*6+u];
            acc[u].x = fmaf(a.x,e.x,fmaf(-a.y,e.y,acc[u].x));
            acc[u].y = fmaf(a.x,e.y,fmaf( a.y,e.x,acc[u].y));
        }
    }
    #pragma unroll
    for (int u = 0; u < 6; u++)
        g_Z1[((size_t)(bo*64+h)*12+kd)*24 + kwg*6+u] = acc[u];
}

// I2: inverse DFT along W, packed. grid 8192, 256 thr
__global__ void k_i2() {
    __shared__ double Zd[288], ZyN[288];     // (z.x,z.x), (-z.y,z.y)  [kd*24+kw]
    __shared__ double Ecs[64], Esc[64];      // (c,s), (s,c)
    int t = threadIdx.x;
    if (t < 64) {
        float c = cospif(t*(1.0f/32.0f)), s = sinpif(t*(1.0f/32.0f));
        Ecs[t] = pk(c,s); Esc[t] = pk(s,c);
    }
    size_t boh = blockIdx.x;
    const double* src = (const double*)g_Z1 + boh*288;
    for (int i = t; i < 288; i += 256) {
        double z = src[i];
        int xb = __double2loint(z), yb = __double2hiint(z);
        Zd[i]  = __hiloint2double(xb, xb);
        ZyN[i] = __hiloint2double(yb, yb ^ 0x80000000);
    }
    __syncthreads();
    int w = t & 63, kdg = t >> 6;
    double acc[3];
    #pragma unroll
    for (int u = 0; u < 3; u++) acc[u] = 0;
    int stp = w*8, id0 = 0, id1 = ((52*w)&63)*8;
    #pragma unroll 4
    for (int kw = 0; kw < 12; kw++) {
        double ecs = ldb(Ecs,id0), esc = ldb(Esc,id0);
        id0 = (id0 + stp) & 511;
        #pragma unroll
        for (int u = 0; u < 3; u++) {
            int z = (kdg*3+u)*24 + kw;
            acc[u] = ffma2(Zd[z], ecs, acc[u]);
            acc[u] = ffma2(ZyN[z], esc, acc[u]);
        }
    }
    #pragma unroll 4
    for (int kw = 12; kw < 24; kw++) {
        double ecs = ldb(Ecs,id1), esc = ldb(Esc,id1);
        id1 = (id1 + stp) & 511;
        #pragma unroll
        for (int u = 0; u < 3; u++) {
            int z = (kdg*3+u)*24 + kw;
            acc[u] = ffma2(Zd[z], ecs, acc[u]);
            acc[u] = ffma2(ZyN[z], esc, acc[u]);
        }
    }
    double* o = (double*)g_Z2 + (boh*64 + w)*12;
    #pragma unroll
    for (int u = 0; u < 3; u++) o[kdg*3+u] = acc[u];
}

// I3: inverse real DFT along D + corr, packed over w-pairs. grid 8192, 256 thr
__global__ void k_i3(float* __restrict__ out) {
    __shared__ double Zx[384], Zy[384];      // [wp*12+kd]: (x_w0,x_w1), (y_w0,y_w1)
    __shared__ float2 E[64];
    int t = threadIdx.x;
    initE(E, t, 256);
    size_t boh = blockIdx.x;
    const float2* src = g_Z2 + boh*768;
    for (int i = t; i < 384; i += 256) {
        int wp = i / 12, kd = i % 12;
        float2 z0 = src[wp*24 + kd], z1 = src[wp*24 + 12 + kd];
        Zx[i] = pk(z0.x, z1.x);
        Zy[i] = pk(z0.y, z1.y);
    }
    __syncthreads();
    int d = t & 63, wg = t >> 6;
    int b = blockIdx.x >> 11, o = (blockIdx.x >> 6) & 31;
    float cv = g_CORR[(b*32+o)*64 + d];
    double CV = pk(cv, cv);
    const double SCd = pk(1.0f/262144.0f, 1.0f/262144.0f);
    double ec[11], esN[11];
    #pragma unroll
    for (int k = 1; k <= 11; k++) {
        float2 e = E[(k*d)&63];
        ec[k-1]  = pk(2.f*e.x, 2.f*e.x);
        esN[k-1] = pk(-2.f*e.y, -2.f*e.y);
    }
    float* orow = out + boh*4096;
    #pragma unroll 2
    for (int j = 0; j < 8; j++) {
        int wp = wg*8 + j;
        const double* zx = &Zx[wp*12];
        const double* zy = &Zy[wp*12];
        double acc = zx[0];
        #pragma unroll
        for (int k = 1; k <= 11; k++) {
            acc = ffma2(zx[k], ec[k-1], acc);
            acc = ffma2(zy[k], esN[k-1], acc);
        }
        acc = ffma2(acc, SCd, CV);
        orow[(2*wp)*64 + d]   = plo(acc);
        orow[(2*wp+1)*64 + d] = phi(acc);
    }
}

// CK1 (unchanged)
__global__ void k_ck1(const float* __restrict__ x) {
    __shared__ float2 E[64];
    int t = threadIdx.x;
    initE(E, t, 256);
    __syncthreads();
    int b = blockIdx.x >> 3, dc = blockIdx.x & 7;
    int c = t >> 3, d = dc*8 + (t&7);
    float ar[9], ai[9];
    #pragma unroll
    for (int i = 0; i < 9; i++) { ar[i]=0; ai[i]=0; }
    for (int s = 0; s < 8; s++) {
        float ts = -1.0f + (2.0f/7.0f)*s;
        float p1 = ts, p2 = 2.0f*ts*ts - 1.0f;
        const float* base = x + ((size_t)(b*32+c)*64 + s)*4096 + d;
        for (int w = 0; w < 64; w++) {
            float xv = base[w*64];
            float2 e1 = E[w], e2 = E[(2*w)&63];
            float m0 = xv, m1 = xv*p1, m2 = xv*p2;
            ar[0] += m0;
            ar[1]=fmaf(m0,e1.x,ar[1]); ai[1]=fmaf(-m0,e1.y,ai[1]);
            ar[2]=fmaf(m0,e2.x,ar[2]); ai[2]=fmaf(-m0,e2.y,ai[2]);
            ar[3] += m1;
            ar[4]=fmaf(m1,e1.x,ar[4]); ai[4]=fmaf(-m1,e1.y,ai[4]);
            ar[5]=fmaf(m1,e2.x,ar[5]); ai[5]=fmaf(-m1,e2.y,ai[5]);
            ar[6] += m2;
            ar[7]=fmaf(m2,e1.x,ar[7]); ai[7]=fmaf(-m2,e1.y,ai[7]);
            ar[8]=fmaf(m2,e2.x,ar[8]); ai[8]=fmaf(-m2,e2.y,ai[8]);
        }
    }
    float* dst = g_CFT + (size_t)(b*64+d)*576 + c*18;
    #pragma unroll
    for (int i = 0; i < 9; i++) {
        dst[i*2]   = ar[i]*0.125f;
        dst[i*2+1] = ai[i]*0.125f;
    }
}

// CK2 (unchanged)
__global__ void k_ck2(const float* __restrict__ W1, const float* __restrict__ b1,
                      const float* __restrict__ W2, const float* __restrict__ b2,
                      const float* __restrict__ corr_scale) {
    __shared__ float fl[576];
    __shared__ float hb[128];
    int n = blockIdx.x, t = threadIdx.x;
    for (int i = t; i < 576; i += 128) fl[i] = g_CFT[(size_t)n*576 + i];
    __syncthreads();
    float acc = b1[t];
    #pragma unroll 4
    for (int k = 0; k < 576; k++)
        acc = fmaf(fl[k], W1[(size_t)k*128 + t], acc);
    hb[t] = 0.5f*acc*(1.0f + erff(acc*0.70710678118654752f));
    __syncthreads();
    if (t < 32) {
        float a2 = b2[t];
        #pragma unroll 4
        for (int k = 0; k < 128; k++)
            a2 = fmaf(hb[k], W2[k*32 + t], a2);
        g_CORR[((n>>6)*32 + t)*64 + (n&63)] = a2*corr_scale[0];
    }
}

extern "C" void kernel_launch(void* const* d_in, const int* in_sizes, int n_in,
                              void* d_out, int out_size) {
    const float* x    = (const float*)d_in[0];
    const float* w1re = (const float*)d_in[1];
    const float* w1im = (const float*)d_in[2];
    const float* w2re = (const float*)d_in[3];
    const float* w2im = (const float*)d_in[4];
    const float* w3re = (const float*)d_in[5];
    const float* w3im = (const float*)d_in[6];
    const float* w4re = (const float*)d_in[7];
    const float* w4im = (const float*)d_in[8];
    const float* W1   = (const float*)d_in[9];
    const float* b1   = (const float*)d_in[10];
    const float* W2   = (const float*)d_in[11];
    const float* b2   = (const float*)d_in[12];
    const float* cs   = (const float*)d_in[13];
    float* out = (float*)d_out;

    static int smem_set = 0;
    const int mix_smem = 110592, big_smem = 66560;
    if (!smem_set) {
        cudaFuncSetAttribute(k_mix, cudaFuncAttributeMaxDynamicSharedMemorySize, mix_smem);
        cudaFuncSetAttribute(k_f1,  cudaFuncAttributeMaxDynamicSharedMemorySize, big_smem);
        cudaFuncSetAttribute(k_f2,  cudaFuncAttributeMaxDynamicSharedMemorySize, big_smem);
        smem_set = 1;
    }

    k_ck1<<<32, 256>>>(x);
    k_ck2<<<256, 128>>>(W1, b1, W2, b2, cs);

    k_f1<<<4096, 128, big_smem>>>(x);
    k_f2<<<1536, 128, big_smem>>>();
    k_f3<<<1536, 288>>>();
    k_mix<<<576, 128, mix_smem>>>(w1re, w1im, w2re, w2im, w3re, w3im, w4re, w4im);
    k_i1<<<1536, 256>>>();
    k_i2<<<8192, 256>>>();
    k_i3<<<8192, 256>>>(out);
}

// round 5
// speedup vs baseline: 1.0156x; 1.0156x over previous
#include <cuda_runtime.h>
#include <math.h>

#define Bn 4
#define Cn 32
#define On 32
#define MD 12
#define MHW 24

__device__ float2 g_X1[Bn*Cn*64*MD*64];
__device__ float2 g_X2[Bn*Cn*MHW*MD*64];
__device__ float2 g_X3[Bn*Cn*MD*MHW*MHW];
__device__ float2 g_Y [Bn*On*MD*MHW*MHW];
__device__ float2 g_Z1[Bn*On*64*MD*MHW];
__device__ float2 g_Z2[Bn*On*64*64*MD];
__device__ float  g_CFTP[8][256][576];
__device__ float  g_CORR[Bn*On*64];

__device__ __forceinline__ double ffma2(double a, double b, double c) {
    unsigned long long r;
    asm("fma.rn.f32x2 %0, %1, %2, %3;" : "=l"(r)
        : "l"(__double_as_longlong(a)), "l"(__double_as_longlong(b)), "l"(__double_as_longlong(c)));
    return __longlong_as_double(r);
}
__device__ __forceinline__ double pk(float lo, float hi) {
    return __hiloint2double(__float_as_int(hi), __float_as_int(lo));
}
__device__ __forceinline__ float plo(double d) { return __int_as_float(__double2loint(d)); }
__device__ __forceinline__ float phi(double d) { return __int_as_float(__double2hiint(d)); }
__device__ __forceinline__ double ldb(const double* b, int off) {
    return *(const double*)((const char*)b + off);
}
__device__ __forceinline__ void initE(float2* E, int t, int nthr) {
    for (int i = t; i < 64; i += nthr)
        E[i] = make_float2(cospif(i * (1.0f/32.0f)), sinpif(i * (1.0f/32.0f)));
}

// F1: real DFT along D. grid 4096 (2 rows), 256 thr, static smem 33.3KB
__global__ void __launch_bounds__(256) k_f1(const float* __restrict__ x) {
    __shared__ float xt[2*4160];             // [hh][w*65+d] plain floats
    __shared__ double E2[64];                // (c,-s)
    int t = threadIdx.x;
    if (t < 64) E2[t] = pk(cospif(t*(1.0f/32.0f)), -sinpif(t*(1.0f/32.0f)));
    const float4* xr4 = (const float4*)(x + (size_t)blockIdx.x * 8192);
    for (int i = t; i < 2048; i += 256) {
        float4 v = xr4[i];
        int hh = i >> 10, r = i & 1023;
        float* p = &xt[hh*4160 + (r>>4)*65 + (r&15)*4];
        p[0]=v.x; p[1]=v.y; p[2]=v.z; p[3]=v.w;
    }
    __syncthreads();
    int hh = t >> 7, jg = (t >> 5) & 3, wg = t & 31, kd0 = jg*3;
    const float* xrow = &xt[hh*4160];
    double a0[2], a1[2], a2[2];
    #pragma unroll
    for (int j = 0; j < 2; j++) { a0[j]=0; a1[j]=0; a2[j]=0; }
    int i0=0, i1=0, i2=0, s0=kd0*8, s1=s0+8, s2=s0+16;
    #pragma unroll 8
    for (int d = 0; d < 64; d++) {
        double e0 = ldb(E2,i0), e1 = ldb(E2,i1), e2 = ldb(E2,i2);
        i0=(i0+s0)&511; i1=(i1+s1)&511; i2=(i2+s2)&511;
        #pragma unroll
        for (int j = 0; j < 2; j++) {
            float v = xrow[(wg + j*32)*65 + d];
            double xv = pk(v, v);
            a0[j]=ffma2(xv,e0,a0[j]); a1[j]=ffma2(xv,e1,a1[j]); a2[j]=ffma2(xv,e2,a2[j]);
        }
    }
    double* o = (double*)g_X1 + (size_t)(blockIdx.x*2 + hh) * 768;
    #pragma unroll
    for (int j = 0; j < 2; j++) {
        int w = wg + j*32;
        o[kd0*64+w]=a0[j]; o[(kd0+1)*64+w]=a1[j]; o[(kd0+2)*64+w]=a2[j];
    }
}

// F2: DFT along W. grid 1536=(bc,kd), 256 thr, smem 34.3KB
__global__ void __launch_bounds__(256) k_f2() {
    __shared__ double A[4160];               // [w*65+h]
    __shared__ double2 Et2[64];              // ((c,c),(s,s))
    int t = threadIdx.x;
    if (t < 64) {
        float c = cospif(t*(1.0f/32.0f)), s = sinpif(t*(1.0f/32.0f));
        Et2[t] = make_double2(pk(c,c), pk(s,s));
    }
    int bc = blockIdx.x / 12, kd = blockIdx.x % 12;
    const double* src = (const double*)g_X1 + (size_t)bc*64*768 + kd*64;
    for (int i = t; i < 4096; i += 256) {
        int h = i >> 6, w = i & 63;
        A[w*65+h] = src[(size_t)h*768 + w];
    }
    __syncthreads();
    int hx = t & 63, kwg = t >> 6;
    double acc[6]; int idx[6], stp[6];
    #pragma unroll
    for (int u = 0; u < 6; u++) {
        int kw = kwg*6+u;
        stp[u] = (kw + (kw>=12 ? 40 : 0))*16; idx[u]=0; acc[u]=0;
    }
    #pragma unroll 4
    for (int w = 0; w < 64; w++) {
        double a = A[w*65+hx];
        double asw = pk(phi(a), -plo(a));    // (ay, -ax)
        #pragma unroll
        for (int u = 0; u < 6; u++) {
            double2 e = *(const double2*)((const char*)Et2 + idx[u]);
            idx[u] = (idx[u] + stp[u]) & 1023;
            acc[u] = ffma2(a, e.x, acc[u]);
            acc[u] = ffma2(asw, e.y, acc[u]);
        }
    }
    #pragma unroll
    for (int u = 0; u < 6; u++)
        ((double*)g_X2)[((size_t)(bc*24 + kwg*6+u)*12 + kd)*64 + hx] = acc[u];
}

// F3: DFT along H. grid 1536, 288 thr (unchanged)
__global__ void k_f3() {
    __shared__ float2 Bt[24*65];
    __shared__ float2 E[64];
    int t = threadIdx.x;
    initE(E, t, 288);
    int bc = blockIdx.x / 12, kd = blockIdx.x % 12;
    for (int i = t; i < 24*64; i += 288)
        Bt[(i>>6)*65 + (i&63)] = g_X2[((size_t)(bc*24 + (i>>6))*12 + kd)*64 + (i&63)];
    __syncthreads();
    int kw = t % 24, kh2 = t / 24;
    float r0=0,i0=0,r1=0,i1=0;
    for (int h = 0; h < 64; h++) {
        float2 a = Bt[kw*65+h];
        float2 e0 = E[(kh2*h)&63];
        float2 e1 = E[((kh2+52)*h)&63];
        r0 = fmaf(a.x,e0.x,fmaf( a.y,e0.y,r0));
        i0 = fmaf(a.y,e0.x,fmaf(-a.x,e0.y,i0));
        r1 = fmaf(a.x,e1.x,fmaf( a.y,e1.y,r1));
        i1 = fmaf(a.y,e1.x,fmaf(-a.x,e1.y,i1));
    }
    float2* o = g_X3 + (size_t)(bc*12 + kd)*576;
    o[kh2*24+kw] = make_float2(r0,i0);
    o[(kh2+12)*24+kw] = make_float2(r1,i1);
}

// MIX. grid 576, 256 thr (kd halved per thread), dyn smem 110592
__global__ void __launch_bounds__(256) k_mix(
        const float* __restrict__ w1re, const float* __restrict__ w1im,
        const float* __restrict__ w2re, const float* __restrict__ w2im,
        const float* __restrict__ w3re, const float* __restrict__ w3im,
        const float* __restrict__ w4re, const float* __restrict__ w4im) {
    extern __shared__ float sm[];
    float*  Wre = sm;
    float*  Wim = sm + 12288;
    float2* X3s = (float2*)(sm + 24576);
    const float* wres[4] = {w1re, w2re, w3re, w4re};
    const float* wims[4] = {w1im, w2im, w3im, w4im};
    int t = threadIdx.x;
    int q = blockIdx.x / 144, mm = blockIdx.x % 144;
    int m1 = mm / 12, m2 = mm % 12;
    int mhw = (m1 + (q&1)*12)*24 + m2 + ((q>>1)&1)*12;
    const float* wre = wres[q];
    const float* wim = wims[q];
    for (int idx = t; idx < 12288; idx += 256) {
        int io = idx / 12, kd = idx % 12;
        size_t g = (size_t)io*1728 + m1*144 + m2*12 + kd;
        int sl = ((io>>5)*12 + kd)*32 + (io&31);
        Wre[sl] = wre[g]; Wim[sl] = wim[g];
    }
    for (int idx = t; idx < 1536; idx += 256)
        X3s[idx] = g_X3[(size_t)idx*576 + mhw];
    __syncthreads();
    int o = t & 31, b = (t >> 5) & 3, kdh = t >> 7;
    float2 acc[6];
    #pragma unroll
    for (int u = 0; u < 6; u++) acc[u] = make_float2(0,0);
    for (int i = 0; i < 32; i++) {
        int xb = (b*32+i)*12 + kdh*6, wb = i*384 + kdh*192 + o;
        #pragma unroll
        for (int u = 0; u < 6; u++) {
            float2 a = X3s[xb+u];
            float wr = Wre[wb+u*32], wi = Wim[wb+u*32];
            acc[u].x = fmaf(a.x,wr,fmaf(-a.y,wi,acc[u].x));
            acc[u].y = fmaf(a.x,wi,fmaf( a.y,wr,acc[u].y));
        }
    }
    #pragma unroll
    for (int u = 0; u < 6; u++)
        g_Y[((size_t)(b*32+o)*12 + kdh*6+u)*576 + mhw] = acc[u];
}

// I1: inverse DFT along H. grid 1536, 256 thr (unchanged)
__global__ void k_i1() {
    __shared__ float2 Ys[576];
    __shared__ float2 E[64];
    int t = threadIdx.x;
    initE(E, t, 256);
    int bo = blockIdx.x / 12, kd = blockIdx.x % 12;
    for (int i = t; i < 576; i += 256)
        Ys[i] = g_Y[(size_t)(bo*12+kd)*576 + i];
    __syncthreads();
    int h = t & 63, kwg = t >> 6;
    float2 acc[6];
    #pragma unroll
    for (int u = 0; u < 6; u++) acc[u] = make_float2(0,0);
    for (int kh = 0; kh < 24; kh++) {
        float2 e = E[((kh + (kh>=12?40:0))*h)&63];
        #pragma unroll
        for (int u = 0; u < 6; u++) {
            float2 a = Ys[kh*24 + kwg*6+u];
            acc[u].x = fmaf(a.x,e.x,fmaf(-a.y,e.y,acc[u].x));
            acc[u].y = fmaf(a.x,e.y,fmaf( a.y,e.x,acc[u].y));
        }
    }
    #pragma unroll
    for (int u = 0; u < 6; u++)
        g_Z1[((size_t)(bo*64+h)*12+kd)*24 + kwg*6+u] = acc[u];
}

// I2: inverse DFT along W, packed. grid 8192, 256 thr (unchanged)
__global__ void k_i2() {
    __shared__ double Zd[288], ZyN[288];
    __shared__ double Ecs[64], Esc[64];
    int t = threadIdx.x;
    if (t < 64) {
        float c = cospif(t*(1.0f/32.0f)), s = sinpif(t*(1.0f/32.0f));
        Ecs[t] = pk(c,s); Esc[t] = pk(s,c);
    }
    size_t boh = blockIdx.x;
    const double* src = (const double*)g_Z1 + boh*288;
    for (int i = t; i < 288; i += 256) {
        double z = src[i];
        int xb = __double2loint(z), yb = __double2hiint(z);
        Zd[i]  = __hiloint2double(xb, xb);
        ZyN[i] = __hiloint2double(yb, yb ^ 0x80000000);
    }
    __syncthreads();
    int w = t & 63, kdg = t >> 6;
    double acc[3];
    #pragma unroll
    for (int u = 0; u < 3; u++) acc[u] = 0;
    int stp = w*8, id0 = 0, id1 = ((52*w)&63)*8;
    #pragma unroll 4
    for (int kw = 0; kw < 12; kw++) {
        double ecs = ldb(Ecs,id0), esc = ldb(Esc,id0);
        id0 = (id0 + stp) & 511;
        #pragma unroll
        for (int u = 0; u < 3; u++) {
            int z = (kdg*3+u)*24 + kw;
            acc[u] = ffma2(Zd[z], ecs, acc[u]);
            acc[u] = ffma2(ZyN[z], esc, acc[u]);
        }
    }
    #pragma unroll 4
    for (int kw = 12; kw < 24; kw++) {
        double ecs = ldb(Ecs,id1), esc = ldb(Esc,id1);
        id1 = (id1 + stp) & 511;
        #pragma unroll
        for (int u = 0; u < 3; u++) {
            int z = (kdg*3+u)*24 + kw;
            acc[u] = ffma2(Zd[z], ecs, acc[u]);
            acc[u] = ffma2(ZyN[z], esc, acc[u]);
        }
    }
    double* o = (double*)g_Z2 + (boh*64 + w)*12;
    #pragma unroll
    for (int u = 0; u < 3; u++) o[kdg*3+u] = acc[u];
}

// I3: inverse real DFT along D + corr, packed over w-pairs. grid 8192, 256 thr
__global__ void k_i3(float* __restrict__ out) {
    __shared__ double Zx[384], Zy[384];
    __shared__ float2 E[64];
    int t = threadIdx.x;
    initE(E, t, 256);
    size_t boh = blockIdx.x;
    const float2* src = g_Z2 + boh*768;
    for (int i = t; i < 384; i += 256) {
        int wp = i / 12, kd = i % 12;
        float2 z0 = src[wp*24 + kd], z1 = src[wp*24 + 12 + kd];
        Zx[i] = pk(z0.x, z1.x);
        Zy[i] = pk(z0.y, z1.y);
    }
    __syncthreads();
    int d = t & 63, wg = t >> 6;
    int b = blockIdx.x >> 11, o = (blockIdx.x >> 6) & 31;
    float cv = g_CORR[(b*32+o)*64 + d];
    double CV = pk(cv, cv);
    const double SCd = pk(1.0f/262144.0f, 1.0f/262144.0f);
    double ec[11], esN[11];
    #pragma unroll
    for (int k = 1; k <= 11; k++) {
        float2 e = E[(k*d)&63];
        ec[k-1]  = pk(2.f*e.x, 2.f*e.x);
        esN[k-1] = pk(-2.f*e.y, -2.f*e.y);
    }
    float* orow = out + boh*4096;
    #pragma unroll 2
    for (int j = 0; j < 8; j++) {
        int wp = wg*8 + j;
        const double* zx = &Zx[wp*12];
        const double* zy = &Zy[wp*12];
        double acc = zx[0];
        #pragma unroll
        for (int k = 1; k <= 11; k++) {
            acc = ffma2(zx[k], ec[k-1], acc);
            acc = ffma2(zy[k], esN[k-1], acc);
        }
        acc = ffma2(acc, SCd, CV);
        orow[(2*wp)*64 + d]   = plo(acc);
        orow[(2*wp+1)*64 + d] = phi(acc);
    }
}

// CK1: per-segment partials. grid 256 = (b,dc,s), 256 thr
__global__ void k_ck1(const float* __restrict__ x) {
    __shared__ float2 E[64];
    int t = threadIdx.x;
    initE(E, t, 256);
    __syncthreads();
    int bid = blockIdx.x;
    int b = bid >> 6, dc = (bid >> 3) & 7, s = bid & 7;
    int c = t >> 3, d = dc*8 + (t & 7);
    float ts = -1.0f + (2.0f/7.0f)*s;
    float p1 = ts, p2 = 2.0f*ts*ts - 1.0f;
    float ar[9], ai[9];
    #pragma unroll
    for (int i = 0; i < 9; i++) { ar[i]=0; ai[i]=0; }
    const float* base = x + ((size_t)(b*32+c)*64 + s)*4096 + d;
    for (int w = 0; w < 64; w++) {
        float xv = base[w*64];
        float2 e1 = E[w], e2 = E[(2*w)&63];
        float m0 = xv, m1 = xv*p1, m2 = xv*p2;
        ar[0] += m0;
        ar[1]=fmaf(m0,e1.x,ar[1]); ai[1]=fmaf(-m0,e1.y,ai[1]);
        ar[2]=fmaf(m0,e2.x,ar[2]); ai[2]=fmaf(-m0,e2.y,ai[2]);
        ar[3] += m1;
        ar[4]=fmaf(m1,e1.x,ar[4]); ai[4]=fmaf(-m1,e1.y,ai[4]);
        ar[5]=fmaf(m1,e2.x,ar[5]); ai[5]=fmaf(-m1,e2.y,ai[5]);
        ar[6] += m2;
        ar[7]=fmaf(m2,e1.x,ar[7]); ai[7]=fmaf(-m2,e1.y,ai[7]);
        ar[8]=fmaf(m2,e2.x,ar[8]); ai[8]=fmaf(-m2,e2.y,ai[8]);
    }
    float* dst = &g_CFTP[s][b*64+d][c*18];
    #pragma unroll
    for (int i = 0; i < 9; i++) {
        dst[i*2]   = ar[i]*0.125f;
        dst[i*2+1] = ai[i]*0.125f;
    }
}

// CK2: sum partials + MLP. grid 256, 128 thr
__global__ void k_ck2(const float* __restrict__ W1, const float* __restrict__ b1,
                      const float* __restrict__ W2, const float* __restrict__ b2,
                      const float* __restrict__ corr_scale) {
    __shared__ float fl[576];
    __shared__ float hb[128];
    int n = blockIdx.x, t = threadIdx.x;
    for (int i = t; i < 576; i += 128) {
        float v = 0;
        #pragma unroll
        for (int s = 0; s < 8; s++) v += g_CFTP[s][n][i];
        fl[i] = v;
    }
    __syncthreads();
    float acc = b1[t];
    #pragma unroll 4
    for (int k = 0; k < 576; k++)
        acc = fmaf(fl[k], W1[(size_t)k*128 + t], acc);
    hb[t] = 0.5f*acc*(1.0f + erff(acc*0.70710678118654752f));
    __syncthreads();
    if (t < 32) {
        float a2 = b2[t];
        #pragma unroll 4
        for (int k = 0; k < 128; k++)
            a2 = fmaf(hb[k], W2[k*32 + t], a2);
        g_CORR[((n>>6)*32 + t)*64 + (n&63)] = a2*corr_scale[0];
    }
}

extern "C" void kernel_launch(void* const* d_in, const int* in_sizes, int n_in,
                              void* d_out, int out_size) {
    const float* x    = (const float*)d_in[0];
    const float* w1re = (const float*)d_in[1];
    const float* w1im = (const float*)d_in[2];
    const float* w2re = (const float*)d_in[3];
    const float* w2im = (const float*)d_in[4];
    const float* w3re = (const float*)d_in[5];
    const float* w3im = (const float*)d_in[6];
    const float* w4re = (const float*)d_in[7];
    const float* w4im = (const float*)d_in[8];
    const float* W1   = (const float*)d_in[9];
    const float* b1   = (const float*)d_in[10];
    const float* W2   = (const float*)d_in[11];
    const float* b2   = (const float*)d_in[12];
    const float* cs   = (const float*)d_in[13];
    float* out = (float*)d_out;

    static int smem_set = 0;
    const int mix_smem = 110592;
    if (!smem_set) {
        cudaFuncSetAttribute(k_mix, cudaFuncAttributeMaxDynamicSharedMemorySize, mix_smem);
        smem_set = 1;
    }

    k_ck1<<<256, 256>>>(x);
    k_ck2<<<256, 128>>>(W1, b1, W2, b2, cs);

    k_f1<<<4096, 256>>>(x);
    k_f2<<<1536, 256>>>();
    k_f3<<<1536, 288>>>();
    k_mix<<<576, 256, mix_smem>>>(w1re, w1im, w2re, w2im, w3re, w3im, w4re, w4im);
    k_i1<<<1536, 256>>>();
    k_i2<<<8192, 256>>>();
    k_i3<<<8192, 256>>>(out);
}

// round 6
// speedup vs baseline: 1.5237x; 1.5003x over previous
#include <cuda_runtime.h>
#include <math.h>

#define Bn 4
#define Cn 32
#define On 32
#define MD 12
#define MHW 24

__device__ float2 g_X1[Bn*Cn*64*MD*64];
__device__ float2 g_X3[Bn*Cn*MD*MHW*MHW];
__device__ float2 g_Y [Bn*On*MD*MHW*MHW];
__device__ float2 g_Z1[Bn*On*64*MD*MHW];
__device__ float  g_CFTP[8][256][576];
__device__ float  g_CORR[Bn*On*64];

__device__ __forceinline__ double ffma2(double a, double b, double c) {
    unsigned long long r;
    asm("fma.rn.f32x2 %0, %1, %2, %3;" : "=l"(r)
        : "l"(__double_as_longlong(a)), "l"(__double_as_longlong(b)), "l"(__double_as_longlong(c)));
    return __longlong_as_double(r);
}
__device__ __forceinline__ double pk(float lo, float hi) {
    return __hiloint2double(__float_as_int(hi), __float_as_int(lo));
}
__device__ __forceinline__ float plo(double d) { return __int_as_float(__double2loint(d)); }
__device__ __forceinline__ float phi(double d) { return __int_as_float(__double2hiint(d)); }
__device__ __forceinline__ double ldb(const double* b, int off) {
    return *(const double*)((const char*)b + off);
}
__device__ __forceinline__ void initE(float2* E, int t, int nthr) {
    for (int i = t; i < 64; i += nthr)
        E[i] = make_float2(cospif(i * (1.0f/32.0f)), sinpif(i * (1.0f/32.0f)));
}

// F1: real DFT along D. grid 4096 (2 rows), 256 thr (unchanged from R4)
__global__ void __launch_bounds__(256) k_f1(const float* __restrict__ x) {
    __shared__ float xt[2*4160];
    __shared__ double E2[64];
    int t = threadIdx.x;
    if (t < 64) E2[t] = pk(cospif(t*(1.0f/32.0f)), -sinpif(t*(1.0f/32.0f)));
    const float4* xr4 = (const float4*)(x + (size_t)blockIdx.x * 8192);
    for (int i = t; i < 2048; i += 256) {
        float4 v = xr4[i];
        int hh = i >> 10, r = i & 1023;
        float* p = &xt[hh*4160 + (r>>4)*65 + (r&15)*4];
        p[0]=v.x; p[1]=v.y; p[2]=v.z; p[3]=v.w;
    }
    __syncthreads();
    int hh = t >> 7, jg = (t >> 5) & 3, wg = t & 31, kd0 = jg*3;
    const float* xrow = &xt[hh*4160];
    double a0[2], a1[2], a2[2];
    #pragma unroll
    for (int j = 0; j < 2; j++) { a0[j]=0; a1[j]=0; a2[j]=0; }
    int i0=0, i1=0, i2=0, s0=kd0*8, s1=s0+8, s2=s0+16;
    #pragma unroll 8
    for (int d = 0; d < 64; d++) {
        double e0 = ldb(E2,i0), e1 = ldb(E2,i1), e2 = ldb(E2,i2);
        i0=(i0+s0)&511; i1=(i1+s1)&511; i2=(i2+s2)&511;
        #pragma unroll
        for (int j = 0; j < 2; j++) {
            float v = xrow[(wg + j*32)*65 + d];
            double xv = pk(v, v);
            a0[j]=ffma2(xv,e0,a0[j]); a1[j]=ffma2(xv,e1,a1[j]); a2[j]=ffma2(xv,e2,a2[j]);
        }
    }
    double* o = (double*)g_X1 + (size_t)(blockIdx.x*2 + hh) * 768;
    #pragma unroll
    for (int j = 0; j < 2; j++) {
        int w = wg + j*32;
        o[kd0*64+w]=a0[j]; o[(kd0+1)*64+w]=a1[j]; o[(kd0+2)*64+w]=a2[j];
    }
}

// F23: fused DFT along W (24 modes) + DFT along H (24 modes).
// grid 1536=(bc,kd), 256 thr, static smem ~47.3KB
__global__ void __launch_bounds__(256) k_f23() {
    __shared__ double A[4160];        // [w*65+h]
    __shared__ double B2[1560];       // [kw*65+h]
    __shared__ double2 Et2[64];       // ((c,c),(s,s))
    __shared__ float2 E[64];
    int t = threadIdx.x;
    if (t < 64) {
        float c = cospif(t*(1.0f/32.0f)), s = sinpif(t*(1.0f/32.0f));
        Et2[t] = make_double2(pk(c,c), pk(s,s));
        E[t] = make_float2(c, s);
    }
    int bc = blockIdx.x / 12, kd = blockIdx.x % 12;
    const double* src = (const double*)g_X1 + (size_t)bc*64*768 + kd*64;
    for (int i = t; i < 4096; i += 256) {
        int h = i >> 6, w = i & 63;
        A[w*65+h] = src[(size_t)h*768 + w];
    }
    __syncthreads();
    // f2 part: thread = hx(0..31) x kwg(0..7); h in {hx,hx+32}, kw in {3*kwg..+2}
    {
        int hx = t & 31, kwg = t >> 5;
        double ac0[3], ac1[3]; int idx[3], stp[3];
        #pragma unroll
        for (int u = 0; u < 3; u++) {
            int kw = kwg*3+u;
            stp[u] = (kw + (kw>=12 ? 40 : 0))*16; idx[u]=0; ac0[u]=0; ac1[u]=0;
        }
        #pragma unroll 4
        for (int w = 0; w < 64; w++) {
            double a0 = A[w*65+hx], a1 = A[w*65+hx+32];
            double s0 = pk(phi(a0), -plo(a0));
            double s1 = pk(phi(a1), -plo(a1));
            #pragma unroll
            for (int u = 0; u < 3; u++) {
                double2 e = *(const double2*)((const char*)Et2 + idx[u]);
                idx[u] = (idx[u] + stp[u]) & 1023;
                ac0[u] = ffma2(a0, e.x, ac0[u]);
                ac0[u] = ffma2(s0, e.y, ac0[u]);
                ac1[u] = ffma2(a1, e.x, ac1[u]);
                ac1[u] = ffma2(s1, e.y, ac1[u]);
            }
        }
        #pragma unroll
        for (int u = 0; u < 3; u++) {
            int kw = kwg*3+u;
            B2[kw*65+hx]    = ac0[u];
            B2[kw*65+hx+32] = ac1[u];
        }
    }
    __syncthreads();
    // f3 part: 288 items (kw, kh2)
    float2* o = g_X3 + (size_t)(bc*12 + kd)*576;
    for (int it = t; it < 288; it += 256) {
        int kw = it % 24, kh2 = it / 24;
        float r0=0,i0=0,r1=0,i1=0;
        int e0i = 0, e1i = 0;
        int e0s = kh2*8, e1s = ((kh2+52)*8) & 511;
        #pragma unroll 4
        for (int h = 0; h < 64; h++) {
            double ad = B2[kw*65+h];
            float ax = plo(ad), ay = phi(ad);
            float2 e0 = *(const float2*)((const char*)E + e0i);
            float2 e1 = *(const float2*)((const char*)E + e1i);
            e0i = (e0i + e0s) & 511;
            e1i = (e1i + e1s) & 511;
            r0 = fmaf(ax,e0.x,fmaf( ay,e0.y,r0));
            i0 = fmaf(ay,e0.x,fmaf(-ax,e0.y,i0));
            r1 = fmaf(ax,e1.x,fmaf( ay,e1.y,r1));
            i1 = fmaf(ay,e1.x,fmaf(-ax,e1.y,i1));
        }
        o[kh2*24+kw]      = make_float2(r0,i0);
        o[(kh2+12)*24+kw] = make_float2(r1,i1);
    }
}

// MIX. grid 576, 256 thr, dyn smem 110592 (unchanged)
__global__ void __launch_bounds__(256) k_mix(
        const float* __restrict__ w1re, const float* __restrict__ w1im,
        const float* __restrict__ w2re, const float* __restrict__ w2im,
        const float* __restrict__ w3re, const float* __restrict__ w3im,
        const float* __restrict__ w4re, const float* __restrict__ w4im) {
    extern __shared__ float sm[];
    float*  Wre = sm;
    float*  Wim = sm + 12288;
    float2* X3s = (float2*)(sm + 24576);
    const float* wres[4] = {w1re, w2re, w3re, w4re};
    const float* wims[4] = {w1im, w2im, w3im, w4im};
    int t = threadIdx.x;
    int q = blockIdx.x / 144, mm = blockIdx.x % 144;
    int m1 = mm / 12, m2 = mm % 12;
    int mhw = (m1 + (q&1)*12)*24 + m2 + ((q>>1)&1)*12;
    const float* wre = wres[q];
    const float* wim = wims[q];
    for (int idx = t; idx < 12288; idx += 256) {
        int io = idx / 12, kd = idx % 12;
        size_t g = (size_t)io*1728 + m1*144 + m2*12 + kd;
        int sl = ((io>>5)*12 + kd)*32 + (io&31);
        Wre[sl] = wre[g]; Wim[sl] = wim[g];
    }
    for (int idx = t; idx < 1536; idx += 256)
        X3s[idx] = g_X3[(size_t)idx*576 + mhw];
    __syncthreads();
    int o = t & 31, b = (t >> 5) & 3, kdh = t >> 7;
    float2 acc[6];
    #pragma unroll
    for (int u = 0; u < 6; u++) acc[u] = make_float2(0,0);
    for (int i = 0; i < 32; i++) {
        int xb = (b*32+i)*12 + kdh*6, wb = i*384 + kdh*192 + o;
        #pragma unroll
        for (int u = 0; u < 6; u++) {
            float2 a = X3s[xb+u];
            float wr = Wre[wb+u*32], wi = Wim[wb+u*32];
            acc[u].x = fmaf(a.x,wr,fmaf(-a.y,wi,acc[u].x));
            acc[u].y = fmaf(a.x,wi,fmaf( a.y,wr,acc[u].y));
        }
    }
    #pragma unroll
    for (int u = 0; u < 6; u++)
        g_Y[((size_t)(b*32+o)*12 + kdh*6+u)*576 + mhw] = acc[u];
}

// I1: inverse DFT along H. grid 1536, 256 thr (unchanged)
__global__ void k_i1() {
    __shared__ float2 Ys[576];
    __shared__ float2 E[64];
    int t = threadIdx.x;
    initE(E, t, 256);
    int bo = blockIdx.x / 12, kd = blockIdx.x % 12;
    for (int i = t; i < 576; i += 256)
        Ys[i] = g_Y[(size_t)(bo*12+kd)*576 + i];
    __syncthreads();
    int h = t & 63, kwg = t >> 6;
    float2 acc[6];
    #pragma unroll
    for (int u = 0; u < 6; u++) acc[u] = make_float2(0,0);
    for (int kh = 0; kh < 24; kh++) {
        float2 e = E[((kh + (kh>=12?40:0))*h)&63];
        #pragma unroll
        for (int u = 0; u < 6; u++) {
            float2 a = Ys[kh*24 + kwg*6+u];
            acc[u].x = fmaf(a.x,e.x,fmaf(-a.y,e.y,acc[u].x));
            acc[u].y = fmaf(a.x,e.y,fmaf( a.y,e.x,acc[u].y));
        }
    }
    #pragma unroll
    for (int u = 0; u < 6; u++)
        g_Z1[((size_t)(bo*64+h)*12+kd)*24 + kwg*6+u] = acc[u];
}

// I23: fused inverse DFT along W + real inverse DFT along D + corr epilogue.
// grid 8192 = (b,o,h), 256 thr, smem ~12.5KB
__global__ void __launch_bounds__(256) k_i23(float* __restrict__ out) {
    __shared__ double Zd[288], ZyN[288];     // (z.x,z.x), (-z.y,z.y)
    __shared__ double Zw[768];               // [w*12+kd] packed (re,im)
    __shared__ double Ecs[64], Esc[64];
    __shared__ float2 E[64];
    int t = threadIdx.x;
    if (t < 64) {
        float c = cospif(t*(1.0f/32.0f)), s = sinpif(t*(1.0f/32.0f));
        Ecs[t] = pk(c,s); Esc[t] = pk(s,c);
        E[t] = make_float2(c, s);
    }
    size_t boh = blockIdx.x;
    const double* src = (const double*)g_Z1 + boh*288;
    for (int i = t; i < 288; i += 256) {
        double z = src[i];
        int xb = __double2loint(z), yb = __double2hiint(z);
        Zd[i]  = __hiloint2double(xb, xb);
        ZyN[i] = __hiloint2double(yb, yb ^ 0x80000000);
    }
    __syncthreads();
    // i2 part: thread (w = t&63, kdg = t>>6), 3 kd each
    {
        int w = t & 63, kdg = t >> 6;
        double acc[3];
        #pragma unroll
        for (int u = 0; u < 3; u++) acc[u] = 0;
        int stp = w*8, id0 = 0, id1 = ((52*w)&63)*8;
        #pragma unroll 4
        for (int kw = 0; kw < 12; kw++) {
            double ecs = ldb(Ecs,id0), esc = ldb(Esc,id0);
            id0 = (id0 + stp) & 511;
            #pragma unroll
            for (int u = 0; u < 3; u++) {
                int z = (kdg*3+u)*24 + kw;
                acc[u] = ffma2(Zd[z], ecs, acc[u]);
                acc[u] = ffma2(ZyN[z], esc, acc[u]);
            }
        }
        #pragma unroll 4
        for (int kw = 12; kw < 24; kw++) {
            double ecs = ldb(Ecs,id1), esc = ldb(Esc,id1);
            id1 = (id1 + stp) & 511;
            #pragma unroll
            for (int u = 0; u < 3; u++) {
                int z = (kdg*3+u)*24 + kw;
                acc[u] = ffma2(Zd[z], ecs, acc[u]);
                acc[u] = ffma2(ZyN[z], esc, acc[u]);
            }
        }
        #pragma unroll
        for (int u = 0; u < 3; u++) Zw[w*12 + kdg*3+u] = acc[u];
    }
    __syncthreads();
    // i3 part: thread (d = t&63, wg = t>>6), 16 w each
    int d = t & 63, wg = t >> 6;
    int b = blockIdx.x >> 11, o = (blockIdx.x >> 6) & 31;
    float cv = g_CORR[(b*32+o)*64 + d];
    const float SC = 1.0f/262144.0f;
    double F2[11];
    #pragma unroll
    for (int k = 1; k <= 11; k++) {
        float2 e = E[(k*d)&63];
        F2[k-1] = pk(2.f*e.x, -2.f*e.y);     // (2c, -2s)
    }
    float* orow = out + boh*4096;
    #pragma unroll 2
    for (int j = 0; j < 16; j++) {
        int w = wg*16 + j;
        const double* z = &Zw[w*12];
        double z0 = z[0];
        double acc = __hiloint2double(0, __double2loint(z0));  // (x0, 0)
        #pragma unroll
        for (int k = 1; k <= 11; k++)
            acc = ffma2(z[k], F2[k-1], acc);
        orow[w*64 + d] = fmaf(SC, plo(acc) + phi(acc), cv);
    }
}

// CK1: per-segment partials. grid 256, 256 thr (unchanged)
__global__ void k_ck1(const float* __restrict__ x) {
    __shared__ float2 E[64];
    int t = threadIdx.x;
    initE(E, t, 256);
    __syncthreads();
    int bid = blockIdx.x;
    int b = bid >> 6, dc = (bid >> 3) & 7, s = bid & 7;
    int c = t >> 3, d = dc*8 + (t & 7);
    float ts = -1.0f + (2.0f/7.0f)*s;
    float p1 = ts, p2 = 2.0f*ts*ts - 1.0f;
    float ar[9], ai[9];
    #pragma unroll
    for (int i = 0; i < 9; i++) { ar[i]=0; ai[i]=0; }
    const float* base = x + ((size_t)(b*32+c)*64 + s)*4096 + d;
    for (int w = 0; w < 64; w++) {
        float xv = base[w*64];
        float2 e1 = E[w], e2 = E[(2*w)&63];
        float m0 = xv, m1 = xv*p1, m2 = xv*p2;
        ar[0] += m0;
        ar[1]=fmaf(m0,e1.x,ar[1]); ai[1]=fmaf(-m0,e1.y,ai[1]);
        ar[2]=fmaf(m0,e2.x,ar[2]); ai[2]=fmaf(-m0,e2.y,ai[2]);
        ar[3] += m1;
        ar[4]=fmaf(m1,e1.x,ar[4]); ai[4]=fmaf(-m1,e1.y,ai[4]);
        ar[5]=fmaf(m1,e2.x,ar[5]); ai[5]=fmaf(-m1,e2.y,ai[5]);
        ar[6] += m2;
        ar[7]=fmaf(m2,e1.x,ar[7]); ai[7]=fmaf(-m2,e1.y,ai[7]);
        ar[8]=fmaf(m2,e2.x,ar[8]); ai[8]=fmaf(-m2,e2.y,ai[8]);
    }
    float* dst = &g_CFTP[s][b*64+d][c*18];
    #pragma unroll
    for (int i = 0; i < 9; i++) {
        dst[i*2]   = ar[i]*0.125f;
        dst[i*2+1] = ai[i]*0.125f;
    }
}

// CK2: sum partials + MLP. grid 256, 128 thr (unchanged)
__global__ void k_ck2(const float* __restrict__ W1, const float* __restrict__ b1,
                      const float* __restrict__ W2, const float* __restrict__ b2,
                      const float* __restrict__ corr_scale) {
    __shared__ float fl[576];
    __shared__ float hb[128];
    int n = blockIdx.x, t = threadIdx.x;
    for (int i = t; i < 576; i += 128) {
        float v = 0;
        #pragma unroll
        for (int s = 0; s < 8; s++) v += g_CFTP[s][n][i];
        fl[i] = v;
    }
    __syncthreads();
    float acc = b1[t];
    #pragma unroll 4
    for (int k = 0; k < 576; k++)
        acc = fmaf(fl[k], W1[(size_t)k*128 + t], acc);
    hb[t] = 0.5f*acc*(1.0f + erff(acc*0.70710678118654752f));
    __syncthreads();
    if (t < 32) {
        float a2 = b2[t];
        #pragma unroll 4
        for (int k = 0; k < 128; k++)
            a2 = fmaf(hb[k], W2[k*32 + t], a2);
        g_CORR[((n>>6)*32 + t)*64 + (n&63)] = a2*corr_scale[0];
    }
}

extern "C" void kernel_launch(void* const* d_in, const int* in_sizes, int n_in,
                              void* d_out, int out_size) {
    const float* x    = (const float*)d_in[0];
    const float* w1re = (const float*)d_in[1];
    const float* w1im = (const float*)d_in[2];
    const float* w2re = (const float*)d_in[3];
    const float* w2im = (const float*)d_in[4];
    const float* w3re = (const float*)d_in[5];
    const float* w3im = (const float*)d_in[6];
    const float* w4re = (const float*)d_in[7];
    const float* w4im = (const float*)d_in[8];
    const float* W1   = (const float*)d_in[9];
    const float* b1   = (const float*)d_in[10];
    const float* W2   = (const float*)d_in[11];
    const float* b2   = (const float*)d_in[12];
    const float* cs   = (const float*)d_in[13];
    float* out = (float*)d_out;

    static int smem_set = 0;
    const int mix_smem = 110592;
    if (!smem_set) {
        cudaFuncSetAttribute(k_mix, cudaFuncAttributeMaxDynamicSharedMemorySize, mix_smem);
        smem_set = 1;
    }

    k_ck1<<<256, 256>>>(x);
    k_ck2<<<256, 128>>>(W1, b1, W2, b2, cs);

    k_f1<<<4096, 256>>>(x);
    k_f23<<<1536, 256>>>();
    k_mix<<<576, 256, mix_smem>>>(w1re, w1im, w2re, w2im, w3re, w3im, w4re, w4im);
    k_i1<<<1536, 256>>>();
    k_i23<<<8192, 256>>>(out);
}

// round 7
// speedup vs baseline: 1.7024x; 1.1173x over previous
#include <cuda_runtime.h>
#include <math.h>

#define Bn 4
#define Cn 32
#define On 32
#define MD 12
#define MHW 24

__device__ float2 g_X1[Bn*Cn*64*MD*64];
__device__ float2 g_X3[Bn*Cn*MD*MHW*MHW];
__device__ float2 g_Y [Bn*On*MD*MHW*MHW];
__device__ float2 g_Z1[Bn*On*64*MD*MHW];
__device__ float  g_CFTP[8][256][576];
__device__ float  g_CORR[Bn*On*64];

__device__ __forceinline__ double ffma2(double a, double b, double c) {
    unsigned long long r;
    asm("fma.rn.f32x2 %0, %1, %2, %3;" : "=l"(r)
        : "l"(__double_as_longlong(a)), "l"(__double_as_longlong(b)), "l"(__double_as_longlong(c)));
    return __longlong_as_double(r);
}
__device__ __forceinline__ double pk(float lo, float hi) {
    return __hiloint2double(__float_as_int(hi), __float_as_int(lo));
}
__device__ __forceinline__ float plo(double d) { return __int_as_float(__double2loint(d)); }
__device__ __forceinline__ float phi(double d) { return __int_as_float(__double2hiint(d)); }
__device__ __forceinline__ double ldb(const double* b, int off) {
    return *(const double*)((const char*)b + off);
}
__device__ __forceinline__ void initE(float2* E, int t, int nthr) {
    for (int i = t; i < 64; i += nthr)
        E[i] = make_float2(cospif(i * (1.0f/32.0f)), sinpif(i * (1.0f/32.0f)));
}

// F1: real DFT along D, packed over w-pairs. grid 4096 (2 rows), 128 thr
__global__ void __launch_bounds__(128) k_f1(const float* __restrict__ x) {
    __shared__ float xt[2*4224];         // [hh][d*66 + w]
    __shared__ double2 Et[64];           // ((c,c), (-s,-s))
    int t = threadIdx.x;
    if (t < 64) {
        float c = cospif(t*(1.0f/32.0f)), s = sinpif(t*(1.0f/32.0f));
        Et[t] = make_double2(pk(c,c), pk(-s,-s));
    }
    const float4* xr4 = (const float4*)(x + (size_t)blockIdx.x * 8192);
    for (int i = t; i < 2048; i += 128) {
        float4 v = xr4[i];
        int hh = i >> 10, r = i & 1023;
        int w = r >> 4, d0 = (r & 15) * 4;
        float* base = &xt[hh*4224 + w];
        base[(d0  )*66] = v.x;
        base[(d0+1)*66] = v.y;
        base[(d0+2)*66] = v.z;
        base[(d0+3)*66] = v.w;
    }
    __syncthreads();
    int hh = t >> 6, jg = (t >> 4) & 3, wp0 = t & 15, kd0 = jg*3;
    const float* xrow = &xt[hh*4224];
    double ar[2][3], ai[2][3];
    #pragma unroll
    for (int p = 0; p < 2; p++)
        #pragma unroll
        for (int u = 0; u < 3; u++) { ar[p][u]=0; ai[p][u]=0; }
    int i0=0, i1=0, i2=0;
    int s0=kd0*16, s1=s0+16, s2=s0+32;
    #pragma unroll 4
    for (int d = 0; d < 64; d++) {
        double2 e0 = *(const double2*)((const char*)Et + i0);
        double2 e1 = *(const double2*)((const char*)Et + i1);
        double2 e2 = *(const double2*)((const char*)Et + i2);
        i0=(i0+s0)&1023; i1=(i1+s1)&1023; i2=(i2+s2)&1023;
        #pragma unroll
        for (int p = 0; p < 2; p++) {
            double xv = *(const double*)&xrow[d*66 + (wp0 + p*16)*2];
            ar[p][0]=ffma2(xv,e0.x,ar[p][0]); ai[p][0]=ffma2(xv,e0.y,ai[p][0]);
            ar[p][1]=ffma2(xv,e1.x,ar[p][1]); ai[p][1]=ffma2(xv,e1.y,ai[p][1]);
            ar[p][2]=ffma2(xv,e2.x,ar[p][2]); ai[p][2]=ffma2(xv,e2.y,ai[p][2]);
        }
    }
    double* o = (double*)g_X1 + (size_t)(blockIdx.x*2 + hh) * 768;
    #pragma unroll
    for (int p = 0; p < 2; p++) {
        int w0 = (wp0 + p*16)*2;
        #pragma unroll
        for (int u = 0; u < 3; u++) {
            o[(kd0+u)*64 + w0  ] = pk(plo(ar[p][u]), plo(ai[p][u]));
            o[(kd0+u)*64 + w0+1] = pk(phi(ar[p][u]), phi(ai[p][u]));
        }
    }
}

// F23: fused DFT along W + DFT along H. grid 1536=(bc,kd), 256 thr (unchanged)
__global__ void __launch_bounds__(256) k_f23() {
    __shared__ double A[4160];
    __shared__ double B2[1560];
    __shared__ double2 Et2[64];
    __shared__ float2 E[64];
    int t = threadIdx.x;
    if (t < 64) {
        float c = cospif(t*(1.0f/32.0f)), s = sinpif(t*(1.0f/32.0f));
        Et2[t] = make_double2(pk(c,c), pk(s,s));
        E[t] = make_float2(c, s);
    }
    int bc = blockIdx.x / 12, kd = blockIdx.x % 12;
    const double* src = (const double*)g_X1 + (size_t)bc*64*768 + kd*64;
    for (int i = t; i < 4096; i += 256) {
        int h = i >> 6, w = i & 63;
        A[w*65+h] = src[(size_t)h*768 + w];
    }
    __syncthreads();
    {
        int hx = t & 31, kwg = t >> 5;
        double ac0[3], ac1[3]; int idx[3], stp[3];
        #pragma unroll
        for (int u = 0; u < 3; u++) {
            int kw = kwg*3+u;
            stp[u] = (kw + (kw>=12 ? 40 : 0))*16; idx[u]=0; ac0[u]=0; ac1[u]=0;
        }
        #pragma unroll 4
        for (int w = 0; w < 64; w++) {
            double a0 = A[w*65+hx], a1 = A[w*65+hx+32];
            double s0 = pk(phi(a0), -plo(a0));
            double s1 = pk(phi(a1), -plo(a1));
            #pragma unroll
            for (int u = 0; u < 3; u++) {
                double2 e = *(const double2*)((const char*)Et2 + idx[u]);
                idx[u] = (idx[u] + stp[u]) & 1023;
                ac0[u] = ffma2(a0, e.x, ac0[u]);
                ac0[u] = ffma2(s0, e.y, ac0[u]);
                ac1[u] = ffma2(a1, e.x, ac1[u]);
                ac1[u] = ffma2(s1, e.y, ac1[u]);
            }
        }
        #pragma unroll
        for (int u = 0; u < 3; u++) {
            int kw = kwg*3+u;
            B2[kw*65+hx]    = ac0[u];
            B2[kw*65+hx+32] = ac1[u];
        }
    }
    __syncthreads();
    float2* o = g_X3 + (size_t)(bc*12 + kd)*576;
    for (int it = t; it < 288; it += 256) {
        int kw = it % 24, kh2 = it / 24;
        float r0=0,i0=0,r1=0,i1=0;
        int e0i = 0, e1i = 0;
        int e0s = kh2*8, e1s = ((kh2+52)*8) & 511;
        #pragma unroll 4
        for (int h = 0; h < 64; h++) {
            double ad = B2[kw*65+h];
            float ax = plo(ad), ay = phi(ad);
            float2 e0 = *(const float2*)((const char*)E + e0i);
            float2 e1 = *(const float2*)((const char*)E + e1i);
            e0i = (e0i + e0s) & 511;
            e1i = (e1i + e1s) & 511;
            r0 = fmaf(ax,e0.x,fmaf( ay,e0.y,r0));
            i0 = fmaf(ay,e0.x,fmaf(-ax,e0.y,i0));
            r1 = fmaf(ax,e1.x,fmaf( ay,e1.y,r1));
            i1 = fmaf(ay,e1.x,fmaf(-ax,e1.y,i1));
        }
        o[kh2*24+kw]      = make_float2(r0,i0);
        o[(kh2+12)*24+kw] = make_float2(r1,i1);
    }
}

// MIX. grid 576, 256 thr, dyn smem 110592; float4 weight loads
__global__ void __launch_bounds__(256) k_mix(
        const float* __restrict__ w1re, const float* __restrict__ w1im,
        const float* __restrict__ w2re, const float* __restrict__ w2im,
        const float* __restrict__ w3re, const float* __restrict__ w3im,
        const float* __restrict__ w4re, const float* __restrict__ w4im) {
    extern __shared__ float sm[];
    float*  Wre = sm;
    float*  Wim = sm + 12288;
    float2* X3s = (float2*)(sm + 24576);
    const float* wres[4] = {w1re, w2re, w3re, w4re};
    const float* wims[4] = {w1im, w2im, w3im, w4im};
    int t = threadIdx.x;
    int q = blockIdx.x / 144, mm = blockIdx.x % 144;
    int m1 = mm / 12, m2 = mm % 12;
    int mhw = (m1 + (q&1)*12)*24 + m2 + ((q>>1)&1)*12;
    const float* wre = wres[q];
    const float* wim = wims[q];
    int woff = m1*144 + m2*12;
    for (int idx = t; idx < 3072; idx += 256) {
        int io = idx / 3, r3 = idx - io*3;
        size_t g = (size_t)io*1728 + woff + r3*4;
        float4 vr = *(const float4*)(wre + g);
        float4 vi = *(const float4*)(wim + g);
        int sl = ((io>>5)*12 + r3*4)*32 + (io&31);
        Wre[sl] = vr.x; Wre[sl+32] = vr.y; Wre[sl+64] = vr.z; Wre[sl+96] = vr.w;
        Wim[sl] = vi.x; Wim[sl+32] = vi.y; Wim[sl+64] = vi.z; Wim[sl+96] = vi.w;
    }
    for (int idx = t; idx < 1536; idx += 256)
        X3s[idx] = g_X3[(size_t)idx*576 + mhw];
    __syncthreads();
    int o = t & 31, b = (t >> 5) & 3, kdh = t >> 7;
    float2 acc[6];
    #pragma unroll
    for (int u = 0; u < 6; u++) acc[u] = make_float2(0,0);
    for (int i = 0; i < 32; i++) {
        int xb = (b*32+i)*12 + kdh*6, wb = i*384 + kdh*192 + o;
        #pragma unroll
        for (int u = 0; u < 6; u++) {
            float2 a = X3s[xb+u];
            float wr = Wre[wb+u*32], wi = Wim[wb+u*32];
            acc[u].x = fmaf(a.x,wr,fmaf(-a.y,wi,acc[u].x));
            acc[u].y = fmaf(a.x,wi,fmaf( a.y,wr,acc[u].y));
        }
    }
    #pragma unroll
    for (int u = 0; u < 6; u++)
        g_Y[((size_t)(b*32+o)*12 + kdh*6+u)*576 + mhw] = acc[u];
}

// I1: inverse DFT along H. grid 1536, 256 thr (unchanged)
__global__ void k_i1() {
    __shared__ float2 Ys[576];
    __shared__ float2 E[64];
    int t = threadIdx.x;
    initE(E, t, 256);
    int bo = blockIdx.x / 12, kd = blockIdx.x % 12;
    for (int i = t; i < 576; i += 256)
        Ys[i] = g_Y[(size_t)(bo*12+kd)*576 + i];
    __syncthreads();
    int h = t & 63, kwg = t >> 6;
    float2 acc[6];
    #pragma unroll
    for (int u = 0; u < 6; u++) acc[u] = make_float2(0,0);
    for (int kh = 0; kh < 24; kh++) {
        float2 e = E[((kh + (kh>=12?40:0))*h)&63];
        #pragma unroll
        for (int u = 0; u < 6; u++) {
            float2 a = Ys[kh*24 + kwg*6+u];
            acc[u].x = fmaf(a.x,e.x,fmaf(-a.y,e.y,acc[u].x));
            acc[u].y = fmaf(a.x,e.y,fmaf( a.y,e.x,acc[u].y));
        }
    }
    #pragma unroll
    for (int u = 0; u < 6; u++)
        g_Z1[((size_t)(bo*64+h)*12+kd)*24 + kwg*6+u] = acc[u];
}

// I23: fused inverse DFT along W + real inverse DFT along D + corr.
// grid 8192, 256 thr; kw-pair and kd-pair LDS.128
__global__ void __launch_bounds__(256) k_i23(float* __restrict__ out) {
    __shared__ __align__(16) double Zd[288], ZyN[288];
    __shared__ __align__(16) double Zw[768];
    __shared__ double Ecs[64], Esc[64];
    __shared__ float2 E[64];
    int t = threadIdx.x;
    if (t < 64) {
        float c = cospif(t*(1.0f/32.0f)), s = sinpif(t*(1.0f/32.0f));
        Ecs[t] = pk(c,s); Esc[t] = pk(s,c);
        E[t] = make_float2(c, s);
    }
    size_t boh = blockIdx.x;
    const double* src = (const double*)g_Z1 + boh*288;
    for (int i = t; i < 288; i += 256) {
        double z = src[i];
        int xb = __double2loint(z), yb = __double2hiint(z);
        Zd[i]  = __hiloint2double(xb, xb);
        ZyN[i] = __hiloint2double(yb, yb ^ 0x80000000);
    }
    __syncthreads();
    {
        int w = t & 63, kdg = t >> 6;
        double acc[3];
        #pragma unroll
        for (int u = 0; u < 3; u++) acc[u] = 0;
        int stp = w*8;
        int stp2 = (stp*2) & 511;
        int ia = 0, ib = stp & 511;
        #pragma unroll 2
        for (int kp = 0; kp < 6; kp++) {
            double ecs0 = ldb(Ecs,ia), esc0 = ldb(Esc,ia);
            double ecs1 = ldb(Ecs,ib), esc1 = ldb(Esc,ib);
            ia = (ia + stp2) & 511; ib = (ib + stp2) & 511;
            #pragma unroll
            for (int u = 0; u < 3; u++) {
                double2 zd = *(const double2*)&Zd[(kdg*3+u)*24 + kp*2];
                double2 zn = *(const double2*)&ZyN[(kdg*3+u)*24 + kp*2];
                acc[u] = ffma2(zd.x, ecs0, acc[u]);
                acc[u] = ffma2(zn.x, esc0, acc[u]);
                acc[u] = ffma2(zd.y, ecs1, acc[u]);
                acc[u] = ffma2(zn.y, esc1, acc[u]);
            }
        }
        ia = ((52*w)&63)*8; ib = (ia + stp) & 511;
        #pragma unroll 2
        for (int kp = 0; kp < 6; kp++) {
            double ecs0 = ldb(Ecs,ia), esc0 = ldb(Esc,ia);
            double ecs1 = ldb(Ecs,ib), esc1 = ldb(Esc,ib);
            ia = (ia + stp2) & 511; ib = (ib + stp2) & 511;
            #pragma unroll
            for (int u = 0; u < 3; u++) {
                double2 zd = *(const double2*)&Zd[(kdg*3+u)*24 + 12 + kp*2];
                double2 zn = *(const double2*)&ZyN[(kdg*3+u)*24 + 12 + kp*2];
                acc[u] = ffma2(zd.x, ecs0, acc[u]);
                acc[u] = ffma2(zn.x, esc0, acc[u]);
                acc[u] = ffma2(zd.y, ecs1, acc[u]);
                acc[u] = ffma2(zn.y, esc1, acc[u]);
            }
        }
        #pragma unroll
        for (int u = 0; u < 3; u++) Zw[w*12 + kdg*3+u] = acc[u];
    }
    __syncthreads();
    int d = t & 63, wg = t >> 6;
    int b = blockIdx.x >> 11, o = (blockIdx.x >> 6) & 31;
    float cv = g_CORR[(b*32+o)*64 + d];
    const float SC = 1.0f/262144.0f;
    double F2[12];
    F2[0] = pk(1.f, 0.f);
    #pragma unroll
    for (int k = 1; k <= 11; k++) {
        float2 e = E[(k*d)&63];
        F2[k] = pk(2.f*e.x, -2.f*e.y);
    }
    float* orow = out + boh*4096;
    #pragma unroll 2
    for (int j = 0; j < 16; j++) {
        int w = wg*16 + j;
        const double2* z2 = (const double2*)&Zw[w*12];
        double acc = 0;
        #pragma unroll
        for (int m = 0; m < 6; m++) {
            double2 zz = z2[m];
            acc = ffma2(zz.x, F2[2*m], acc);
            acc = ffma2(zz.y, F2[2*m+1], acc);
        }
        orow[w*64 + d] = fmaf(SC, plo(acc) + phi(acc), cv);
    }
}

// CK1: per-segment partials. grid 256, 256 thr (unchanged)
__global__ void k_ck1(const float* __restrict__ x) {
    __shared__ float2 E[64];
    int t = threadIdx.x;
    initE(E, t, 256);
    __syncthreads();
    int bid = blockIdx.x;
    int b = bid >> 6, dc = (bid >> 3) & 7, s = bid & 7;
    int c = t >> 3, d = dc*8 + (t & 7);
    float ts = -1.0f + (2.0f/7.0f)*s;
    float p1 = ts, p2 = 2.0f*ts*ts - 1.0f;
    float ar[9], ai[9];
    #pragma unroll
    for (int i = 0; i < 9; i++) { ar[i]=0; ai[i]=0; }
    const float* base = x + ((size_t)(b*32+c)*64 + s)*4096 + d;
    for (int w = 0; w < 64; w++) {
        float xv = base[w*64];
        float2 e1 = E[w], e2 = E[(2*w)&63];
        float m0 = xv, m1 = xv*p1, m2 = xv*p2;
        ar[0] += m0;
        ar[1]=fmaf(m0,e1.x,ar[1]); ai[1]=fmaf(-m0,e1.y,ai[1]);
        ar[2]=fmaf(m0,e2.x,ar[2]); ai[2]=fmaf(-m0,e2.y,ai[2]);
        ar[3] += m1;
        ar[4]=fmaf(m1,e1.x,ar[4]); ai[4]=fmaf(-m1,e1.y,ai[4]);
        ar[5]=fmaf(m1,e2.x,ar[5]); ai[5]=fmaf(-m1,e2.y,ai[5]);
        ar[6] += m2;
        ar[7]=fmaf(m2,e1.x,ar[7]); ai[7]=fmaf(-m2,e1.y,ai[7]);
        ar[8]=fmaf(m2,e2.x,ar[8]); ai[8]=fmaf(-m2,e2.y,ai[8]);
    }
    float* dst = &g_CFTP[s][b*64+d][c*18];
    #pragma unroll
    for (int i = 0; i < 9; i++) {
        dst[i*2]   = ar[i]*0.125f;
        dst[i*2+1] = ai[i]*0.125f;
    }
}

// CK2: sum partials + MLP. grid 256, 128 thr (unchanged)
__global__ void k_ck2(const float* __restrict__ W1, const float* __restrict__ b1,
                      const float* __restrict__ W2, const float* __restrict__ b2,
                      const float* __restrict__ corr_scale) {
    __shared__ float fl[576];
    __shared__ float hb[128];
    int n = blockIdx.x, t = threadIdx.x;
    for (int i = t; i < 576; i += 128) {
        float v = 0;
        #pragma unroll
        for (int s = 0; s < 8; s++) v += g_CFTP[s][n][i];
        fl[i] = v;
    }
    __syncthreads();
    float acc = b1[t];
    #pragma unroll 4
    for (int k = 0; k < 576; k++)
        acc = fmaf(fl[k], W1[(size_t)k*128 + t], acc);
    hb[t] = 0.5f*acc*(1.0f + erff(acc*0.70710678118654752f));
    __syncthreads();
    if (t < 32) {
        float a2 = b2[t];
        #pragma unroll 4
        for (int k = 0; k < 128; k++)
            a2 = fmaf(hb[k], W2[k*32 + t], a2);
        g_CORR[((n>>6)*32 + t)*64 + (n&63)] = a2*corr_scale[0];
    }
}

extern "C" void kernel_launch(void* const* d_in, const int* in_sizes, int n_in,
                              void* d_out, int out_size) {
    const float* x    = (const float*)d_in[0];
    const float* w1re = (const float*)d_in[1];
    const float* w1im = (const float*)d_in[2];
    const float* w2re = (const float*)d_in[3];
    const float* w2im = (const float*)d_in[4];
    const float* w3re = (const float*)d_in[5];
    const float* w3im = (const float*)d_in[6];
    const float* w4re = (const float*)d_in[7];
    const float* w4im = (const float*)d_in[8];
    const float* W1   = (const float*)d_in[9];
    const float* b1   = (const float*)d_in[10];
    const float* W2   = (const float*)d_in[11];
    const float* b2   = (const float*)d_in[12];
    const float* cs   = (const float*)d_in[13];
    float* out = (float*)d_out;

    static int smem_set = 0;
    const int mix_smem = 110592;
    if (!smem_set) {
        cudaFuncSetAttribute(k_mix, cudaFuncAttributeMaxDynamicSharedMemorySize, mix_smem);
        smem_set = 1;
    }

    k_ck1<<<256, 256>>>(x);
    k_ck2<<<256, 128>>>(W1, b1, W2, b2, cs);

    k_f1<<<4096, 128>>>(x);
    k_f23<<<1536, 256>>>();
    k_mix<<<576, 256, mix_smem>>>(w1re, w1im, w2re, w2im, w3re, w3im, w4re, w4im);
    k_i1<<<1536, 256>>>();
    k_i23<<<8192, 256>>>(out);
}

// round 8
// speedup vs baseline: 1.8778x; 1.1030x over previous
#include <cuda_runtime.h>
#include <math.h>

#define Bn 4
#define Cn 32
#define On 32
#define MD 12
#define MHW 24

__device__ float2 g_X1[Bn*Cn*64*MD*64];
__device__ float2 g_X3[Bn*Cn*MD*MHW*MHW];
__device__ float2 g_Y [Bn*On*MD*MHW*MHW];
__device__ float2 g_Z1[Bn*On*64*MD*MHW];
__device__ float  g_CFTP[8][256][576];
__device__ float  g_CORR[Bn*On*64];

__device__ __forceinline__ double ffma2(double a, double b, double c) {
    unsigned long long r;
    asm("fma.rn.f32x2 %0, %1, %2, %3;" : "=l"(r)
        : "l"(__double_as_longlong(a)), "l"(__double_as_longlong(b)), "l"(__double_as_longlong(c)));
    return __longlong_as_double(r);
}
__device__ __forceinline__ double add2(double a, double b) {
    unsigned long long r;
    asm("add.rn.f32x2 %0, %1, %2;" : "=l"(r)
        : "l"(__double_as_longlong(a)), "l"(__double_as_longlong(b)));
    return __longlong_as_double(r);
}
__device__ __forceinline__ double pk(float lo, float hi) {
    return __hiloint2double(__float_as_int(hi), __float_as_int(lo));
}
__device__ __forceinline__ float plo(double d) { return __int_as_float(__double2loint(d)); }
__device__ __forceinline__ float phi(double d) { return __int_as_float(__double2hiint(d)); }
__device__ __forceinline__ void initE(float2* E, int t, int nthr) {
    for (int i = t; i < 64; i += nthr)
        E[i] = make_float2(cospif(i * (1.0f/32.0f)), sinpif(i * (1.0f/32.0f)));
}

// F1: real DFT along D, packed over w-pairs. grid 4096, 128 thr (unchanged)
__global__ void __launch_bounds__(128) k_f1(const float* __restrict__ x) {
    __shared__ float xt[2*4224];
    __shared__ double2 Et[64];
    int t = threadIdx.x;
    if (t < 64) {
        float c = cospif(t*(1.0f/32.0f)), s = sinpif(t*(1.0f/32.0f));
        Et[t] = make_double2(pk(c,c), pk(-s,-s));
    }
    const float4* xr4 = (const float4*)(x + (size_t)blockIdx.x * 8192);
    for (int i = t; i < 2048; i += 128) {
        float4 v = xr4[i];
        int hh = i >> 10, r = i & 1023;
        int w = r >> 4, d0 = (r & 15) * 4;
        float* base = &xt[hh*4224 + w];
        base[(d0  )*66] = v.x;
        base[(d0+1)*66] = v.y;
        base[(d0+2)*66] = v.z;
        base[(d0+3)*66] = v.w;
    }
    __syncthreads();
    int hh = t >> 6, jg = (t >> 4) & 3, wp0 = t & 15, kd0 = jg*3;
    const float* xrow = &xt[hh*4224];
    double ar[2][3], ai[2][3];
    #pragma unroll
    for (int p = 0; p < 2; p++)
        #pragma unroll
        for (int u = 0; u < 3; u++) { ar[p][u]=0; ai[p][u]=0; }
    int i0=0, i1=0, i2=0;
    int s0=kd0*16, s1=s0+16, s2=s0+32;
    #pragma unroll 4
    for (int d = 0; d < 64; d++) {
        double2 e0 = *(const double2*)((const char*)Et + i0);
        double2 e1 = *(const double2*)((const char*)Et + i1);
        double2 e2 = *(const double2*)((const char*)Et + i2);
        i0=(i0+s0)&1023; i1=(i1+s1)&1023; i2=(i2+s2)&1023;
        #pragma unroll
        for (int p = 0; p < 2; p++) {
            double xv = *(const double*)&xrow[d*66 + (wp0 + p*16)*2];
            ar[p][0]=ffma2(xv,e0.x,ar[p][0]); ai[p][0]=ffma2(xv,e0.y,ai[p][0]);
            ar[p][1]=ffma2(xv,e1.x,ar[p][1]); ai[p][1]=ffma2(xv,e1.y,ai[p][1]);
            ar[p][2]=ffma2(xv,e2.x,ar[p][2]); ai[p][2]=ffma2(xv,e2.y,ai[p][2]);
        }
    }
    double* o = (double*)g_X1 + (size_t)(blockIdx.x*2 + hh) * 768;
    #pragma unroll
    for (int p = 0; p < 2; p++) {
        int w0 = (wp0 + p*16)*2;
        #pragma unroll
        for (int u = 0; u < 3; u++) {
            o[(kd0+u)*64 + w0  ] = pk(plo(ar[p][u]), plo(ai[p][u]));
            o[(kd0+u)*64 + w0+1] = pk(phi(ar[p][u]), phi(ai[p][u]));
        }
    }
}

// F23: fused DFT along W + H with conjugate-pair factorization.
// grid 1536=(bc,kd), 320 thr
__global__ void __launch_bounds__(320) k_f23() {
    __shared__ double A[4160];        // [w*65+h]
    __shared__ double B2[1560];       // [c*65+h], c = kw index 0..23
    __shared__ double2 T2[64];        // (cc, ss)
    __shared__ float2 E[64];
    int t = threadIdx.x;
    if (t < 64) {
        float c = cospif(t*(1.0f/32.0f)), s = sinpif(t*(1.0f/32.0f));
        T2[t] = make_double2(pk(c,c), pk(s,s));
        E[t] = make_float2(c, s);
    }
    int bc = blockIdx.x / 12, kd = blockIdx.x % 12;
    const double* src = (const double*)g_X1 + (size_t)bc*64*768 + kd*64;
    for (int i = t; i < 4096; i += 320)
        A[(i&63)*65 + (i>>6)] = src[(size_t)(i>>6)*768 + (i&63)];
    __syncthreads();
    // f2 part: pairs (p, 64-p). thread = h(0..63) x g(0..3); g handles p = g*3+1..g*3+3
    if (t < 256) {
        int h = t & 63, g = t >> 6;
        int p0 = g*3 + 1;
        double aA[3] = {0,0,0}, aB[3] = {0,0,0}, acc0 = 0;
        int idx[3], stp[3];
        #pragma unroll
        for (int u = 0; u < 3; u++) { stp[u] = (p0+u)*16; idx[u] = 0; }
        #pragma unroll 4
        for (int w = 0; w < 64; w++) {
            double a = A[w*65+h];
            if (g == 0) acc0 = add2(acc0, a);
            #pragma unroll
            for (int u = 0; u < 3; u++) {
                double2 e = *(const double2*)((const char*)T2 + idx[u]);
                idx[u] = (idx[u] + stp[u]) & 1023;
                aA[u] = ffma2(a, e.x, aA[u]);
                aB[u] = ffma2(a, e.y, aB[u]);
            }
        }
        #pragma unroll
        for (int u = 0; u < 3; u++) {
            int p = p0 + u;
            float Ax = plo(aA[u]), Cx = phi(aA[u]);
            float Dx = plo(aB[u]), Bx = phi(aB[u]);
            if (p < 12) {
                B2[p*65 + h]      = pk(Ax+Bx, Cx-Dx);
                B2[(24-p)*65 + h] = pk(Ax-Bx, Cx+Dx);
            } else {
                B2[12*65 + h]     = pk(Ax-Bx, Cx+Dx);   // kw=52 only
            }
        }
        if (g == 0) B2[h] = acc0;                       // kw=0
    }
    __syncthreads();
    // f3 part: 312 items = 24 kw x 13 (11 pairs + p12 + kh0)
    if (t < 312) {
        int kw = t % 24, pp = t / 24;
        float2* o = g_X3 + (size_t)(bc*12 + kd)*576;
        if (pp < 12) {
            int p = pp + 1;
            float Ax=0, Bx=0, Cx=0, Dx=0;
            int ei = 0, es = (p*8) & 511;
            #pragma unroll 4
            for (int h = 0; h < 64; h++) {
                double ad = B2[kw*65+h];
                float ax = plo(ad), ay = phi(ad);
                float2 e = *(const float2*)((const char*)E + ei);
                ei = (ei + es) & 511;
                Ax = fmaf(ax, e.x, Ax); Dx = fmaf(ax, e.y, Dx);
                Cx = fmaf(ay, e.x, Cx); Bx = fmaf(ay, e.y, Bx);
            }
            if (p < 12) {
                o[p*24 + kw]      = make_float2(Ax+Bx, Cx-Dx);
                o[(24-p)*24 + kw] = make_float2(Ax-Bx, Cx+Dx);
            } else {
                o[12*24 + kw]     = make_float2(Ax-Bx, Cx+Dx);  // kh=52
            }
        } else {  // kh = 0
            float r = 0, im = 0;
            #pragma unroll 4
            for (int h = 0; h < 64; h++) {
                double ad = B2[kw*65+h];
                r += plo(ad); im += phi(ad);
            }
            o[kw] = make_float2(r, im);
        }
    }
}

// MIX. grid 576, 256 thr, dyn smem 110592 (unchanged)
__global__ void __launch_bounds__(256) k_mix(
        const float* __restrict__ w1re, const float* __restrict__ w1im,
        const float* __restrict__ w2re, const float* __restrict__ w2im,
        const float* __restrict__ w3re, const float* __restrict__ w3im,
        const float* __restrict__ w4re, const float* __restrict__ w4im) {
    extern __shared__ float sm[];
    float*  Wre = sm;
    float*  Wim = sm + 12288;
    float2* X3s = (float2*)(sm + 24576);
    const float* wres[4] = {w1re, w2re, w3re, w4re};
    const float* wims[4] = {w1im, w2im, w3im, w4im};
    int t = threadIdx.x;
    int q = blockIdx.x / 144, mm = blockIdx.x % 144;
    int m1 = mm / 12, m2 = mm % 12;
    int mhw = (m1 + (q&1)*12)*24 + m2 + ((q>>1)&1)*12;
    const float* wre = wres[q];
    const float* wim = wims[q];
    int woff = m1*144 + m2*12;
    for (int idx = t; idx < 3072; idx += 256) {
        int io = idx / 3, r3 = idx - io*3;
        size_t g = (size_t)io*1728 + woff + r3*4;
        float4 vr = *(const float4*)(wre + g);
        float4 vi = *(const float4*)(wim + g);
        int sl = ((io>>5)*12 + r3*4)*32 + (io&31);
        Wre[sl] = vr.x; Wre[sl+32] = vr.y; Wre[sl+64] = vr.z; Wre[sl+96] = vr.w;
        Wim[sl] = vi.x; Wim[sl+32] = vi.y; Wim[sl+64] = vi.z; Wim[sl+96] = vi.w;
    }
    for (int idx = t; idx < 1536; idx += 256)
        X3s[idx] = g_X3[(size_t)idx*576 + mhw];
    __syncthreads();
    int o = t & 31, b = (t >> 5) & 3, kdh = t >> 7;
    float2 acc[6];
    #pragma unroll
    for (int u = 0; u < 6; u++) acc[u] = make_float2(0,0);
    for (int i = 0; i < 32; i++) {
        int xb = (b*32+i)*12 + kdh*6, wb = i*384 + kdh*192 + o;
        #pragma unroll
        for (int u = 0; u < 6; u++) {
            float2 a = X3s[xb+u];
            float wr = Wre[wb+u*32], wi = Wim[wb+u*32];
            acc[u].x = fmaf(a.x,wr,fmaf(-a.y,wi,acc[u].x));
            acc[u].y = fmaf(a.x,wi,fmaf( a.y,wr,acc[u].y));
        }
    }
    #pragma unroll
    for (int u = 0; u < 6; u++)
        g_Y[((size_t)(b*32+o)*12 + kdh*6+u)*576 + mhw] = acc[u];
}

// I1: inverse DFT along H, conjugate-paired + packed. grid 1536, 256 thr
__global__ void __launch_bounds__(256) k_i1() {
    __shared__ double Yp[264], Ym[264];      // [ (p-1)*24 + kw ]
    __shared__ double Y0[24], Y52a[24], Y52b[24];
    __shared__ double2 T2[64];
    int t = threadIdx.x;
    if (t < 64) {
        float c = cospif(t*(1.0f/32.0f)), s = sinpif(t*(1.0f/32.0f));
        T2[t] = make_double2(pk(c,c), pk(s,s));
    }
    int bo = blockIdx.x / 12, kd = blockIdx.x % 12;
    const float2* Yr = g_Y + (size_t)(bo*12+kd)*576;
    for (int i = t; i < 312; i += 256) {
        if (i < 264) {
            int p = i/24 + 1, kw = i % 24;
            float2 z1 = Yr[p*24 + kw], z2 = Yr[(24-p)*24 + kw];
            Yp[i] = pk(z1.x + z2.x, z1.y + z2.y);
            Ym[i] = pk(z2.y - z1.y, z1.x - z2.x);
        } else if (i < 288) {
            int kw = i - 264;
            float2 z = Yr[kw];
            Y0[kw] = pk(z.x, z.y);
        } else {
            int kw = i - 288;
            float2 z = Yr[12*24 + kw];
            Y52a[kw] = pk(z.x, z.y);
            Y52b[kw] = pk(-z.y, z.x);
        }
    }
    __syncthreads();
    int h = t & 63, kwg = t >> 6;
    int kw0 = kwg * 6;
    double acc[6];
    #pragma unroll
    for (int u = 0; u < 6; u++) acc[u] = Y0[kw0+u];
    int ei = (h*16) & 1023, es = h*16;
    for (int p = 1; p <= 11; p++) {
        double2 e = *(const double2*)((const char*)T2 + ei);
        ei = (ei + es) & 1023;
        int base = (p-1)*24 + kw0;
        #pragma unroll
        for (int u = 0; u < 6; u++) {
            acc[u] = ffma2(Yp[base+u], e.x, acc[u]);
            acc[u] = ffma2(Ym[base+u], e.y, acc[u]);
        }
    }
    double2 e52 = T2[(52*h) & 63];
    #pragma unroll
    for (int u = 0; u < 6; u++) {
        acc[u] = ffma2(Y52a[kw0+u], e52.x, acc[u]);
        acc[u] = ffma2(Y52b[kw0+u], e52.y, acc[u]);
    }
    double* o = (double*)g_Z1 + ((size_t)(bo*64+h)*12 + kd)*24 + kw0;
    #pragma unroll
    for (int u = 0; u < 6; u++) o[u] = acc[u];
}

// I23: fused inverse DFT along W (paired) + real inverse DFT along D + corr.
// grid 8192, 256 thr
__global__ void __launch_bounds__(256) k_i23(float* __restrict__ out) {
    __shared__ double Zp[132], Zm[132];      // [kd*11 + (p-1)]
    __shared__ double Z0[12], Z52a[12], Z52b[12];
    __shared__ __align__(16) double Zw[768]; // [w*12+kd]
    __shared__ double2 T2[64];
    __shared__ float2 E[64];
    int t = threadIdx.x;
    if (t < 64) {
        float c = cospif(t*(1.0f/32.0f)), s = sinpif(t*(1.0f/32.0f));
        T2[t] = make_double2(pk(c,c), pk(s,s));
        E[t] = make_float2(c, s);
    }
    size_t boh = blockIdx.x;
    const float2* src = g_Z1 + boh*288;
    for (int i = t; i < 144; i += 256) {
        if (i < 132) {
            int kd = i / 11, p = i % 11 + 1;
            float2 z1 = src[kd*24 + p], z2 = src[kd*24 + 24 - p];
            Zp[i] = pk(z1.x + z2.x, z1.y + z2.y);
            Zm[i] = pk(z2.y - z1.y, z1.x - z2.x);
        } else {
            int kd = i - 132;
            float2 z0 = src[kd*24];
            Z0[kd] = pk(z0.x, z0.y);
            float2 zc = src[kd*24 + 12];
            Z52a[kd] = pk(zc.x, zc.y);
            Z52b[kd] = pk(-zc.y, zc.x);
        }
    }
    __syncthreads();
    // i2 part
    {
        int w = t & 63, kdg = t >> 6;
        double acc[3];
        #pragma unroll
        for (int u = 0; u < 3; u++) acc[u] = Z0[kdg*3+u];
        int ei = (w*16) & 1023, es = w*16;
        for (int p = 1; p <= 11; p++) {
            double2 e = *(const double2*)((const char*)T2 + ei);
            ei = (ei + es) & 1023;
            #pragma unroll
            for (int u = 0; u < 3; u++) {
                int idx = (kdg*3+u)*11 + p - 1;
                acc[u] = ffma2(Zp[idx], e.x, acc[u]);
                acc[u] = ffma2(Zm[idx], e.y, acc[u]);
            }
        }
        double2 e52 = T2[(52*w) & 63];
        #pragma unroll
        for (int u = 0; u < 3; u++) {
            acc[u] = ffma2(Z52a[kdg*3+u], e52.x, acc[u]);
            acc[u] = ffma2(Z52b[kdg*3+u], e52.y, acc[u]);
        }
        #pragma unroll
        for (int u = 0; u < 3; u++) Zw[w*12 + kdg*3+u] = acc[u];
    }
    __syncthreads();
    // i3 part (unchanged)
    int d = t & 63, wg = t >> 6;
    int b = blockIdx.x >> 11, o = (blockIdx.x >> 6) & 31;
    float cv = g_CORR[(b*32+o)*64 + d];
    const float SC = 1.0f/262144.0f;
    double F2[12];
    F2[0] = pk(1.f, 0.f);
    #pragma unroll
    for (int k = 1; k <= 11; k++) {
        float2 e = E[(k*d)&63];
        F2[k] = pk(2.f*e.x, -2.f*e.y);
    }
    float* orow = out + boh*4096;
    #pragma unroll 2
    for (int j = 0; j < 16; j++) {
        int w = wg*16 + j;
        const double2* z2 = (const double2*)&Zw[w*12];
        double acc = 0;
        #pragma unroll
        for (int m = 0; m < 6; m++) {
            double2 zz = z2[m];
            acc = ffma2(zz.x, F2[2*m], acc);
            acc = ffma2(zz.y, F2[2*m+1], acc);
        }
        orow[w*64 + d] = fmaf(SC, plo(acc) + phi(acc), cv);
    }
}

// CK1: per-segment partials. grid 256, 256 thr (unchanged)
__global__ void k_ck1(const float* __restrict__ x) {
    __shared__ float2 E[64];
    int t = threadIdx.x;
    initE(E, t, 256);
    __syncthreads();
    int bid = blockIdx.x;
    int b = bid >> 6, dc = (bid >> 3) & 7, s = bid & 7;
    int c = t >> 3, d = dc*8 + (t & 7);
    float ts = -1.0f + (2.0f/7.0f)*s;
    float p1 = ts, p2 = 2.0f*ts*ts - 1.0f;
    float ar[9], ai[9];
    #pragma unroll
    for (int i = 0; i < 9; i++) { ar[i]=0; ai[i]=0; }
    const float* base = x + ((size_t)(b*32+c)*64 + s)*4096 + d;
    for (int w = 0; w < 64; w++) {
        float xv = base[w*64];
        float2 e1 = E[w], e2 = E[(2*w)&63];
        float m0 = xv, m1 = xv*p1, m2 = xv*p2;
        ar[0] += m0;
        ar[1]=fmaf(m0,e1.x,ar[1]); ai[1]=fmaf(-m0,e1.y,ai[1]);
        ar[2]=fmaf(m0,e2.x,ar[2]); ai[2]=fmaf(-m0,e2.y,ai[2]);
        ar[3] += m1;
        ar[4]=fmaf(m1,e1.x,ar[4]); ai[4]=fmaf(-m1,e1.y,ai[4]);
        ar[5]=fmaf(m1,e2.x,ar[5]); ai[5]=fmaf(-m1,e2.y,ai[5]);
        ar[6] += m2;
        ar[7]=fmaf(m2,e1.x,ar[7]); ai[7]=fmaf(-m2,e1.y,ai[7]);
        ar[8]=fmaf(m2,e2.x,ar[8]); ai[8]=fmaf(-m2,e2.y,ai[8]);
    }
    float* dst = &g_CFTP[s][b*64+d][c*18];
    #pragma unroll
    for (int i = 0; i < 9; i++) {
        dst[i*2]   = ar[i]*0.125f;
        dst[i*2+1] = ai[i]*0.125f;
    }
}

// CK2: sum partials + MLP. grid 256, 128 thr (unchanged)
__global__ void k_ck2(const float* __restrict__ W1, const float* __restrict__ b1,
                      const float* __restrict__ W2, const float* __restrict__ b2,
                      const float* __restrict__ corr_scale) {
    __shared__ float fl[576];
    __shared__ float hb[128];
    int n = blockIdx.x, t = threadIdx.x;
    for (int i = t; i < 576; i += 128) {
        float v = 0;
        #pragma unroll
        for (int s = 0; s < 8; s++) v += g_CFTP[s][n][i];
        fl[i] = v;
    }
    __syncthreads();
    float acc = b1[t];
    #pragma unroll 4
    for (int k = 0; k < 576; k++)
        acc = fmaf(fl[k], W1[(size_t)k*128 + t], acc);
    hb[t] = 0.5f*acc*(1.0f + erff(acc*0.70710678118654752f));
    __syncthreads();
    if (t < 32) {
        float a2 = b2[t];
        #pragma unroll 4
        for (int k = 0; k < 128; k++)
            a2 = fmaf(hb[k], W2[k*32 + t], a2);
        g_CORR[((n>>6)*32 + t)*64 + (n&63)] = a2*corr_scale[0];
    }
}

extern "C" void kernel_launch(void* const* d_in, const int* in_sizes, int n_in,
                              void* d_out, int out_size) {
    const float* x    = (const float*)d_in[0];
    const float* w1re = (const float*)d_in[1];
    const float* w1im = (const float*)d_in[2];
    const float* w2re = (const float*)d_in[3];
    const float* w2im = (const float*)d_in[4];
    const float* w3re = (const float*)d_in[5];
    const float* w3im = (const float*)d_in[6];
    const float* w4re = (const float*)d_in[7];
    const float* w4im = (const float*)d_in[8];
    const float* W1   = (const float*)d_in[9];
    const float* b1   = (const float*)d_in[10];
    const float* W2   = (const float*)d_in[11];
    const float* b2   = (const float*)d_in[12];
    const float* cs   = (const float*)d_in[13];
    float* out = (float*)d_out;

    static int smem_set = 0;
    const int mix_smem = 110592;
    if (!smem_set) {
        cudaFuncSetAttribute(k_mix, cudaFuncAttributeMaxDynamicSharedMemorySize, mix_smem);
        smem_set = 1;
    }

    k_ck1<<<256, 256>>>(x);
    k_ck2<<<256, 128>>>(W1, b1, W2, b2, cs);

    k_f1<<<4096, 128>>>(x);
    k_f23<<<1536, 320>>>();
    k_mix<<<576, 256, mix_smem>>>(w1re, w1im, w2re, w2im, w3re, w3im, w4re, w4im);
    k_i1<<<1536, 256>>>();
    k_i23<<<8192, 256>>>(out);
}

// round 9
// speedup vs baseline: 1.8893x; 1.0061x over previous
#include <cuda_runtime.h>
#include <math.h>

#define Bn 4
#define Cn 32
#define On 32
#define MD 12
#define MHW 24

__device__ float2 g_X1[Bn*Cn*64*MD*64];
__device__ float2 g_X3[Bn*Cn*MD*MHW*MHW];
__device__ float2 g_Y [Bn*On*MD*MHW*MHW];
__device__ float2 g_Z1[Bn*On*64*MD*MHW];
__device__ float  g_CFTP[8][256][576];
__device__ float  g_CORR[Bn*On*64];

__device__ __forceinline__ double ffma2(double a, double b, double c) {
    unsigned long long r;
    asm("fma.rn.f32x2 %0, %1, %2, %3;" : "=l"(r)
        : "l"(__double_as_longlong(a)), "l"(__double_as_longlong(b)), "l"(__double_as_longlong(c)));
    return __longlong_as_double(r);
}
__device__ __forceinline__ double add2(double a, double b) {
    unsigned long long r;
    asm("add.rn.f32x2 %0, %1, %2;" : "=l"(r)
        : "l"(__double_as_longlong(a)), "l"(__double_as_longlong(b)));
    return __longlong_as_double(r);
}
__device__ __forceinline__ double pk(float lo, float hi) {
    return __hiloint2double(__float_as_int(hi), __float_as_int(lo));
}
__device__ __forceinline__ float plo(double d) { return __int_as_float(__double2loint(d)); }
__device__ __forceinline__ float phi(double d) { return __int_as_float(__double2hiint(d)); }
__device__ __forceinline__ double ldb(const double* b, int off) {
    return *(const double*)((const char*)b + off);
}
__device__ __forceinline__ void initE(float2* E, int t, int nthr) {
    for (int i = t; i < 64; i += nthr)
        E[i] = make_float2(cospif(i * (1.0f/32.0f)), sinpif(i * (1.0f/32.0f)));
}

// F1: real DFT along D, packed over w-pairs. grid 4096, 128 thr (unchanged)
__global__ void __launch_bounds__(128) k_f1(const float* __restrict__ x) {
    __shared__ float xt[2*4224];
    __shared__ double2 Et[64];
    int t = threadIdx.x;
    if (t < 64) {
        float c = cospif(t*(1.0f/32.0f)), s = sinpif(t*(1.0f/32.0f));
        Et[t] = make_double2(pk(c,c), pk(-s,-s));
    }
    const float4* xr4 = (const float4*)(x + (size_t)blockIdx.x * 8192);
    for (int i = t; i < 2048; i += 128) {
        float4 v = xr4[i];
        int hh = i >> 10, r = i & 1023;
        int w = r >> 4, d0 = (r & 15) * 4;
        float* base = &xt[hh*4224 + w];
        base[(d0  )*66] = v.x;
        base[(d0+1)*66] = v.y;
        base[(d0+2)*66] = v.z;
        base[(d0+3)*66] = v.w;
    }
    __syncthreads();
    int hh = t >> 6, jg = (t >> 4) & 3, wp0 = t & 15, kd0 = jg*3;
    const float* xrow = &xt[hh*4224];
    double ar[2][3], ai[2][3];
    #pragma unroll
    for (int p = 0; p < 2; p++)
        #pragma unroll
        for (int u = 0; u < 3; u++) { ar[p][u]=0; ai[p][u]=0; }
    int i0=0, i1=0, i2=0;
    int s0=kd0*16, s1=s0+16, s2=s0+32;
    #pragma unroll 4
    for (int d = 0; d < 64; d++) {
        double2 e0 = *(const double2*)((const char*)Et + i0);
        double2 e1 = *(const double2*)((const char*)Et + i1);
        double2 e2 = *(const double2*)((const char*)Et + i2);
        i0=(i0+s0)&1023; i1=(i1+s1)&1023; i2=(i2+s2)&1023;
        #pragma unroll
        for (int p = 0; p < 2; p++) {
            double xv = *(const double*)&xrow[d*66 + (wp0 + p*16)*2];
            ar[p][0]=ffma2(xv,e0.x,ar[p][0]); ai[p][0]=ffma2(xv,e0.y,ai[p][0]);
            ar[p][1]=ffma2(xv,e1.x,ar[p][1]); ai[p][1]=ffma2(xv,e1.y,ai[p][1]);
            ar[p][2]=ffma2(xv,e2.x,ar[p][2]); ai[p][2]=ffma2(xv,e2.y,ai[p][2]);
        }
    }
    double* o = (double*)g_X1 + (size_t)(blockIdx.x*2 + hh) * 768;
    #pragma unroll
    for (int p = 0; p < 2; p++) {
        int w0 = (wp0 + p*16)*2;
        #pragma unroll
        for (int u = 0; u < 3; u++) {
            o[(kd0+u)*64 + w0  ] = pk(plo(ar[p][u]), plo(ai[p][u]));
            o[(kd0+u)*64 + w0+1] = pk(phi(ar[p][u]), phi(ai[p][u]));
        }
    }
}

// F23: fused DFT W + H, wavefront-optimized. grid 1536=(bc,kd), 320 thr
__global__ void __launch_bounds__(320) k_f23() {
    __shared__ double A[4160];            // [w*65+h]
    __shared__ float B2r[1560], B2i[1560];// [kw*65+h]
    __shared__ double2 T2[64];            // (cc, ss)
    __shared__ float2 E[64];
    int t = threadIdx.x;
    if (t < 64) {
        float c = cospif(t*(1.0f/32.0f)), s = sinpif(t*(1.0f/32.0f));
        T2[t] = make_double2(pk(c,c), pk(s,s));
        E[t] = make_float2(c, s);
    }
    int bc = blockIdx.x / 12, kd = blockIdx.x % 12;
    const double* src = (const double*)g_X1 + (size_t)bc*64*768 + kd*64;
    for (int i = t; i < 4096; i += 320)
        A[(i&63)*65 + (i>>6)] = src[(size_t)(i>>6)*768 + (i&63)];
    __syncthreads();
    // f2-part: 96 threads: hp = t&31 (h in {hp, hp+32}), pg = t>>5 handles pairs pg*4+1..pg*4+4
    if (t < 96) {
        int hp = t & 31, pg = t >> 5;
        int p0 = pg*4 + 1;
        double aA[4][2], aB[4][2];
        #pragma unroll
        for (int u = 0; u < 4; u++) { aA[u][0]=0; aA[u][1]=0; aB[u][0]=0; aB[u][1]=0; }
        double d0 = 0, d1 = 0;
        int idx[4], stp[4];
        #pragma unroll
        for (int u = 0; u < 4; u++) { stp[u] = (p0+u)*16; idx[u] = 0; }
        #pragma unroll 4
        for (int w = 0; w < 64; w++) {
            double a0 = A[w*65+hp], a1 = A[w*65+hp+32];
            if (pg == 0) { d0 = add2(d0, a0); d1 = add2(d1, a1); }
            #pragma unroll
            for (int u = 0; u < 4; u++) {
                double2 e = *(const double2*)((const char*)T2 + idx[u]);
                idx[u] = (idx[u] + stp[u]) & 1023;
                aA[u][0] = ffma2(a0, e.x, aA[u][0]);
                aB[u][0] = ffma2(a0, e.y, aB[u][0]);
                aA[u][1] = ffma2(a1, e.x, aA[u][1]);
                aB[u][1] = ffma2(a1, e.y, aB[u][1]);
            }
        }
        #pragma unroll
        for (int u = 0; u < 4; u++) {
            int p = p0 + u;
            #pragma unroll
            for (int hh = 0; hh < 2; hh++) {
                int h = hp + hh*32;
                float Ax = plo(aA[u][hh]), Cx = phi(aA[u][hh]);
                float Dx = plo(aB[u][hh]), Bx = phi(aB[u][hh]);
                if (p < 12) {
                    B2r[p*65+h]      = Ax+Bx;  B2i[p*65+h]      = Cx-Dx;
                    B2r[(24-p)*65+h] = Ax-Bx;  B2i[(24-p)*65+h] = Cx+Dx;
                } else {
                    B2r[12*65+h]     = Ax-Bx;  B2i[12*65+h]     = Cx+Dx;
                }
            }
        }
        if (pg == 0) {
            B2r[hp]    = plo(d0); B2i[hp]    = phi(d0);
            B2r[hp+32] = plo(d1); B2i[hp+32] = phi(d1);
        }
    }
    __syncthreads();
    // f3-part: 312 items (kw, pp)
    if (t < 312) {
        int kw = t % 24, pp = t / 24;
        float2* o = g_X3 + (size_t)(bc*12 + kd)*576;
        if (pp < 12) {
            int p = pp + 1;
            float Ax=0, Bx=0, Cx=0, Dx=0;
            int ei = 0, es = (p*8) & 511;
            #pragma unroll 4
            for (int h = 0; h < 64; h++) {
                float ax = B2r[kw*65+h], ay = B2i[kw*65+h];
                float2 e = *(const float2*)((const char*)E + ei);
                ei = (ei + es) & 511;
                Ax = fmaf(ax, e.x, Ax); Dx = fmaf(ax, e.y, Dx);
                Cx = fmaf(ay, e.x, Cx); Bx = fmaf(ay, e.y, Bx);
            }
            if (p < 12) {
                o[p*24 + kw]      = make_float2(Ax+Bx, Cx-Dx);
                o[(24-p)*24 + kw] = make_float2(Ax-Bx, Cx+Dx);
            } else {
                o[12*24 + kw]     = make_float2(Ax-Bx, Cx+Dx);
            }
        } else {
            float r = 0, im = 0;
            #pragma unroll 4
            for (int h = 0; h < 64; h++) { r += B2r[kw*65+h]; im += B2i[kw*65+h]; }
            o[kw] = make_float2(r, im);
        }
    }
}

// MIX. grid 576, 256 thr, dyn smem 110592 (unchanged)
__global__ void __launch_bounds__(256) k_mix(
        const float* __restrict__ w1re, const float* __restrict__ w1im,
        const float* __restrict__ w2re, const float* __restrict__ w2im,
        const float* __restrict__ w3re, const float* __restrict__ w3im,
        const float* __restrict__ w4re, const float* __restrict__ w4im) {
    extern __shared__ float sm[];
    float*  Wre = sm;
    float*  Wim = sm + 12288;
    float2* X3s = (float2*)(sm + 24576);
    const float* wres[4] = {w1re, w2re, w3re, w4re};
    const float* wims[4] = {w1im, w2im, w3im, w4im};
    int t = threadIdx.x;
    int q = blockIdx.x / 144, mm = blockIdx.x % 144;
    int m1 = mm / 12, m2 = mm % 12;
    int mhw = (m1 + (q&1)*12)*24 + m2 + ((q>>1)&1)*12;
    const float* wre = wres[q];
    const float* wim = wims[q];
    int woff = m1*144 + m2*12;
    for (int idx = t; idx < 3072; idx += 256) {
        int io = idx / 3, r3 = idx - io*3;
        size_t g = (size_t)io*1728 + woff + r3*4;
        float4 vr = *(const float4*)(wre + g);
        float4 vi = *(const float4*)(wim + g);
        int sl = ((io>>5)*12 + r3*4)*32 + (io&31);
        Wre[sl] = vr.x; Wre[sl+32] = vr.y; Wre[sl+64] = vr.z; Wre[sl+96] = vr.w;
        Wim[sl] = vi.x; Wim[sl+32] = vi.y; Wim[sl+64] = vi.z; Wim[sl+96] = vi.w;
    }
    for (int idx = t; idx < 1536; idx += 256)
        X3s[idx] = g_X3[(size_t)idx*576 + mhw];
    __syncthreads();
    int o = t & 31, b = (t >> 5) & 3, kdh = t >> 7;
    float2 acc[6];
    #pragma unroll
    for (int u = 0; u < 6; u++) acc[u] = make_float2(0,0);
    for (int i = 0; i < 32; i++) {
        int xb = (b*32+i)*12 + kdh*6, wb = i*384 + kdh*192 + o;
        #pragma unroll
        for (int u = 0; u < 6; u++) {
            float2 a = X3s[xb+u];
            float wr = Wre[wb+u*32], wi = Wim[wb+u*32];
            acc[u].x = fmaf(a.x,wr,fmaf(-a.y,wi,acc[u].x));
            acc[u].y = fmaf(a.x,wi,fmaf( a.y,wr,acc[u].y));
        }
    }
    #pragma unroll
    for (int u = 0; u < 6; u++)
        g_Y[((size_t)(b*32+o)*12 + kdh*6+u)*576 + mhw] = acc[u];
}

// I1: inverse DFT along H, paired; compact float2 twiddle table. grid 1536, 256 thr
__global__ void __launch_bounds__(256) k_i1() {
    __shared__ double Yp[264], Ym[264];
    __shared__ double Y0[24], Y52a[24], Y52b[24];
    __shared__ float2 E[64];
    int t = threadIdx.x;
    initE(E, t, 256);
    int bo = blockIdx.x / 12, kd = blockIdx.x % 12;
    const float2* Yr = g_Y + (size_t)(bo*12+kd)*576;
    for (int i = t; i < 312; i += 256) {
        if (i < 264) {
            int p = i/24 + 1, kw = i % 24;
            float2 z1 = Yr[p*24 + kw], z2 = Yr[(24-p)*24 + kw];
            Yp[i] = pk(z1.x + z2.x, z1.y + z2.y);
            Ym[i] = pk(z2.y - z1.y, z1.x - z2.x);
        } else if (i < 288) {
            int kw = i - 264;
            float2 z = Yr[kw];
            Y0[kw] = pk(z.x, z.y);
        } else {
            int kw = i - 288;
            float2 z = Yr[12*24 + kw];
            Y52a[kw] = pk(z.x, z.y);
            Y52b[kw] = pk(-z.y, z.x);
        }
    }
    __syncthreads();
    int h = t & 63, kwg = t >> 6;
    int kw0 = kwg * 6;
    double acc[6];
    #pragma unroll
    for (int u = 0; u < 6; u++) acc[u] = Y0[kw0+u];
    int ei = (h*8) & 511, es = h*8;
    for (int p = 1; p <= 11; p++) {
        float2 ef = *(const float2*)((const char*)E + ei);
        ei = (ei + es) & 511;
        double ex = pk(ef.x, ef.x), ey = pk(ef.y, ef.y);
        int base = (p-1)*24 + kw0;
        #pragma unroll
        for (int u = 0; u < 6; u++) {
            acc[u] = ffma2(Yp[base+u], ex, acc[u]);
            acc[u] = ffma2(Ym[base+u], ey, acc[u]);
        }
    }
    float2 e52f = E[(52*h) & 63];
    double e52x = pk(e52f.x, e52f.x), e52y = pk(e52f.y, e52f.y);
    #pragma unroll
    for (int u = 0; u < 6; u++) {
        acc[u] = ffma2(Y52a[kw0+u], e52x, acc[u]);
        acc[u] = ffma2(Y52b[kw0+u], e52y, acc[u]);
    }
    double* o = (double*)g_Z1 + ((size_t)(bo*64+h)*12 + kd)*24 + kw0;
    #pragma unroll
    for (int u = 0; u < 6; u++) o[u] = acc[u];
}

// I23: fused inverse W (paired) + real inverse D + corr. grid 8192, 256 thr
__global__ void __launch_bounds__(256) k_i23(float* __restrict__ out) {
    __shared__ double Zp[132], Zm[132];
    __shared__ double Z0[12], Z52a[12], Z52b[12];
    __shared__ __align__(16) double Zw[768];
    __shared__ float2 E[64];
    int t = threadIdx.x;
    initE(E, t, 256);
    size_t boh = blockIdx.x;
    const float2* src = g_Z1 + boh*288;
    for (int i = t; i < 144; i += 256) {
        if (i < 132) {
            int kd = i / 11, p = i % 11 + 1;
            float2 z1 = src[kd*24 + p], z2 = src[kd*24 + 24 - p];
            Zp[i] = pk(z1.x + z2.x, z1.y + z2.y);
            Zm[i] = pk(z2.y - z1.y, z1.x - z2.x);
        } else {
            int kd = i - 132;
            float2 z0 = src[kd*24];
            Z0[kd] = pk(z0.x, z0.y);
            float2 zc = src[kd*24 + 12];
            Z52a[kd] = pk(zc.x, zc.y);
            Z52b[kd] = pk(-zc.y, zc.x);
        }
    }
    __syncthreads();
    {
        int w = t & 63, kdg = t >> 6;
        double acc[3];
        #pragma unroll
        for (int u = 0; u < 3; u++) acc[u] = Z0[kdg*3+u];
        int ei = (w*8) & 511, es = w*8;
        for (int p = 1; p <= 11; p++) {
            float2 ef = *(const float2*)((const char*)E + ei);
            ei = (ei + es) & 511;
            double ex = pk(ef.x, ef.x), ey = pk(ef.y, ef.y);
            #pragma unroll
            for (int u = 0; u < 3; u++) {
                int idx = (kdg*3+u)*11 + p - 1;
                acc[u] = ffma2(Zp[idx], ex, acc[u]);
                acc[u] = ffma2(Zm[idx], ey, acc[u]);
            }
        }
        float2 e52f = E[(52*w) & 63];
        double e52x = pk(e52f.x, e52f.x), e52y = pk(e52f.y, e52f.y);
        #pragma unroll
        for (int u = 0; u < 3; u++) {
            acc[u] = ffma2(Z52a[kdg*3+u], e52x, acc[u]);
            acc[u] = ffma2(Z52b[kdg*3+u], e52y, acc[u]);
        }
        #pragma unroll
        for (int u = 0; u < 3; u++) Zw[w*12 + kdg*3+u] = acc[u];
    }
    __syncthreads();
    int d = t & 63, wg = t >> 6;
    int b = blockIdx.x >> 11, o = (blockIdx.x >> 6) & 31;
    float cv = g_CORR[(b*32+o)*64 + d];
    const float SC = 1.0f/262144.0f;
    double F2[12];
    F2[0] = pk(1.f, 0.f);
    #pragma unroll
    for (int k = 1; k <= 11; k++) {
        float2 e = E[(k*d)&63];
        F2[k] = pk(2.f*e.x, -2.f*e.y);
    }
    float* orow = out + boh*4096;
    #pragma unroll 2
    for (int j = 0; j < 16; j++) {
        int w = wg*16 + j;
        const double2* z2 = (const double2*)&Zw[w*12];
        double acc = 0;
        #pragma unroll
        for (int m = 0; m < 6; m++) {
            double2 zz = z2[m];
            acc = ffma2(zz.x, F2[2*m], acc);
            acc = ffma2(zz.y, F2[2*m+1], acc);
        }
        orow[w*64 + d] = fmaf(SC, plo(acc) + phi(acc), cv);
    }
}

// CK1: per-segment partials. grid 256, 256 thr (unchanged)
__global__ void k_ck1(const float* __restrict__ x) {
    __shared__ float2 E[64];
    int t = threadIdx.x;
    initE(E, t, 256);
    __syncthreads();
    int bid = blockIdx.x;
    int b = bid >> 6, dc = (bid >> 3) & 7, s = bid & 7;
    int c = t >> 3, d = dc*8 + (t & 7);
    float ts = -1.0f + (2.0f/7.0f)*s;
    float p1 = ts, p2 = 2.0f*ts*ts - 1.0f;
    float ar[9], ai[9];
    #pragma unroll
    for (int i = 0; i < 9; i++) { ar[i]=0; ai[i]=0; }
    const float* base = x + ((size_t)(b*32+c)*64 + s)*4096 + d;
    for (int w = 0; w < 64; w++) {
        float xv = base[w*64];
        float2 e1 = E[w], e2 = E[(2*w)&63];
        float m0 = xv, m1 = xv*p1, m2 = xv*p2;
        ar[0] += m0;
        ar[1]=fmaf(m0,e1.x,ar[1]); ai[1]=fmaf(-m0,e1.y,ai[1]);
        ar[2]=fmaf(m0,e2.x,ar[2]); ai[2]=fmaf(-m0,e2.y,ai[2]);
        ar[3] += m1;
        ar[4]=fmaf(m1,e1.x,ar[4]); ai[4]=fmaf(-m1,e1.y,ai[4]);
        ar[5]=fmaf(m1,e2.x,ar[5]); ai[5]=fmaf(-m1,e2.y,ai[5]);
        ar[6] += m2;
        ar[7]=fmaf(m2,e1.x,ar[7]); ai[7]=fmaf(-m2,e1.y,ai[7]);
        ar[8]=fmaf(m2,e2.x,ar[8]); ai[8]=fmaf(-m2,e2.y,ai[8]);
    }
    float* dst = &g_CFTP[s][b*64+d][c*18];
    #pragma unroll
    for (int i = 0; i < 9; i++) {
        dst[i*2]   = ar[i]*0.125f;
        dst[i*2+1] = ai[i]*0.125f;
    }
}

// CK2: sum partials + MLP. grid 256, 128 thr (unchanged)
__global__ void k_ck2(const float* __restrict__ W1, const float* __restrict__ b1,
                      const float* __restrict__ W2, const float* __restrict__ b2,
                      const float* __restrict__ corr_scale) {
    __shared__ float fl[576];
    __shared__ float hb[128];
    int n = blockIdx.x, t = threadIdx.x;
    for (int i = t; i < 576; i += 128) {
        float v = 0;
        #pragma unroll
        for (int s = 0; s < 8; s++) v += g_CFTP[s][n][i];
        fl[i] = v;
    }
    __syncthreads();
    float acc = b1[t];
    #pragma unroll 4
    for (int k = 0; k < 576; k++)
        acc = fmaf(fl[k], W1[(size_t)k*128 + t], acc);
    hb[t] = 0.5f*acc*(1.0f + erff(acc*0.70710678118654752f));
    __syncthreads();
    if (t < 32) {
        float a2 = b2[t];
        #pragma unroll 4
        for (int k = 0; k < 128; k++)
            a2 = fmaf(hb[k], W2[k*32 + t], a2);
        g_CORR[((n>>6)*32 + t)*64 + (n&63)] = a2*corr_scale[0];
    }
}

extern "C" void kernel_launch(void* const* d_in, const int* in_sizes, int n_in,
                              void* d_out, int out_size) {
    const float* x    = (const float*)d_in[0];
    const float* w1re = (const float*)d_in[1];
    const float* w1im = (const float*)d_in[2];
    const float* w2re = (const float*)d_in[3];
    const float* w2im = (const float*)d_in[4];
    const float* w3re = (const float*)d_in[5];
    const float* w3im = (const float*)d_in[6];
    const float* w4re = (const float*)d_in[7];
    const float* w4im = (const float*)d_in[8];
    const float* W1   = (const float*)d_in[9];
    const float* b1   = (const float*)d_in[10];
    const float* W2   = (const float*)d_in[11];
    const float* b2   = (const float*)d_in[12];
    const float* cs   = (const float*)d_in[13];
    float* out = (float*)d_out;

    static int smem_set = 0;
    const int mix_smem = 110592;
    if (!smem_set) {
        cudaFuncSetAttribute(k_mix, cudaFuncAttributeMaxDynamicSharedMemorySize, mix_smem);
        smem_set = 1;
    }

    k_ck1<<<256, 256>>>(x);
    k_ck2<<<256, 128>>>(W1, b1, W2, b2, cs);

    k_f1<<<4096, 128>>>(x);
    k_f23<<<1536, 320>>>();
    k_mix<<<576, 256, mix_smem>>>(w1re, w1im, w2re, w2im, w3re, w3im, w4re, w4im);
    k_i1<<<1536, 256>>>();
    k_i23<<<8192, 256>>>(out);
}

// round 10
// speedup vs baseline: 1.9488x; 1.0315x over previous
#include <cuda_runtime.h>
#include <math.h>

#define Bn 4
#define Cn 32
#define On 32
#define MD 12
#define MHW 24

__device__ float2 g_X1[Bn*Cn*64*MD*64];
__device__ float2 g_X3[Bn*Cn*MD*MHW*MHW];
__device__ float2 g_Y [Bn*On*MD*MHW*MHW];
__device__ float2 g_Z1[Bn*On*64*MD*MHW];
__device__ float  g_CFTP[8][256][576];
__device__ float  g_CORR[Bn*On*64];

__device__ __forceinline__ double ffma2(double a, double b, double c) {
    unsigned long long r;
    asm("fma.rn.f32x2 %0, %1, %2, %3;" : "=l"(r)
        : "l"(__double_as_longlong(a)), "l"(__double_as_longlong(b)), "l"(__double_as_longlong(c)));
    return __longlong_as_double(r);
}
__device__ __forceinline__ double add2(double a, double b) {
    unsigned long long r;
    asm("add.rn.f32x2 %0, %1, %2;" : "=l"(r)
        : "l"(__double_as_longlong(a)), "l"(__double_as_longlong(b)));
    return __longlong_as_double(r);
}
__device__ __forceinline__ double pk(float lo, float hi) {
    return __hiloint2double(__float_as_int(hi), __float_as_int(lo));
}
__device__ __forceinline__ float plo(double d) { return __int_as_float(__double2loint(d)); }
__device__ __forceinline__ float phi(double d) { return __int_as_float(__double2hiint(d)); }
__device__ __forceinline__ void initE(float2* E, int t, int nthr) {
    for (int i = t; i < 64; i += nthr)
        E[i] = make_float2(cospif(i * (1.0f/32.0f)), sinpif(i * (1.0f/32.0f)));
}

// F1: real DFT along D, packed over w-pairs. grid 4096, 128 thr (unchanged)
__global__ void __launch_bounds__(128) k_f1(const float* __restrict__ x) {
    __shared__ float xt[2*4224];
    __shared__ double2 Et[64];
    int t = threadIdx.x;
    if (t < 64) {
        float c = cospif(t*(1.0f/32.0f)), s = sinpif(t*(1.0f/32.0f));
        Et[t] = make_double2(pk(c,c), pk(-s,-s));
    }
    const float4* xr4 = (const float4*)(x + (size_t)blockIdx.x * 8192);
    for (int i = t; i < 2048; i += 128) {
        float4 v = xr4[i];
        int hh = i >> 10, r = i & 1023;
        int w = r >> 4, d0 = (r & 15) * 4;
        float* base = &xt[hh*4224 + w];
        base[(d0  )*66] = v.x;
        base[(d0+1)*66] = v.y;
        base[(d0+2)*66] = v.z;
        base[(d0+3)*66] = v.w;
    }
    __syncthreads();
    int hh = t >> 6, jg = (t >> 4) & 3, wp0 = t & 15, kd0 = jg*3;
    const float* xrow = &xt[hh*4224];
    double ar[2][3], ai[2][3];
    #pragma unroll
    for (int p = 0; p < 2; p++)
        #pragma unroll
        for (int u = 0; u < 3; u++) { ar[p][u]=0; ai[p][u]=0; }
    int i0=0, i1=0, i2=0;
    int s0=kd0*16, s1=s0+16, s2=s0+32;
    #pragma unroll 4
    for (int d = 0; d < 64; d++) {
        double2 e0 = *(const double2*)((const char*)Et + i0);
        double2 e1 = *(const double2*)((const char*)Et + i1);
        double2 e2 = *(const double2*)((const char*)Et + i2);
        i0=(i0+s0)&1023; i1=(i1+s1)&1023; i2=(i2+s2)&1023;
        #pragma unroll
        for (int p = 0; p < 2; p++) {
            double xv = *(const double*)&xrow[d*66 + (wp0 + p*16)*2];
            ar[p][0]=ffma2(xv,e0.x,ar[p][0]); ai[p][0]=ffma2(xv,e0.y,ai[p][0]);
            ar[p][1]=ffma2(xv,e1.x,ar[p][1]); ai[p][1]=ffma2(xv,e1.y,ai[p][1]);
            ar[p][2]=ffma2(xv,e2.x,ar[p][2]); ai[p][2]=ffma2(xv,e2.y,ai[p][2]);
        }
    }
    double* o = (double*)g_X1 + (size_t)(blockIdx.x*2 + hh) * 768;
    #pragma unroll
    for (int p = 0; p < 2; p++) {
        int w0 = (wp0 + p*16)*2;
        #pragma unroll
        for (int u = 0; u < 3; u++) {
            o[(kd0+u)*64 + w0  ] = pk(plo(ar[p][u]), plo(ai[p][u]));
            o[(kd0+u)*64 + w0+1] = pk(phi(ar[p][u]), phi(ai[p][u]));
        }
    }
}

// F23: fused DFT W + H. f2-part: R7 layout (256 thr, 3 pairs each);
// f3-part: split float planes. grid 1536=(bc,kd), 320 thr
__global__ void __launch_bounds__(320) k_f23() {
    __shared__ double A[4160];            // [w*65+h]
    __shared__ float B2r[1560], B2i[1560];// [kw*65+h]
    __shared__ double2 T2[64];            // (cc, ss)
    __shared__ float2 E[64];
    int t = threadIdx.x;
    if (t < 64) {
        float c = cospif(t*(1.0f/32.0f)), s = sinpif(t*(1.0f/32.0f));
        T2[t] = make_double2(pk(c,c), pk(s,s));
        E[t] = make_float2(c, s);
    }
    int bc = blockIdx.x / 12, kd = blockIdx.x % 12;
    const double* src = (const double*)g_X1 + (size_t)bc*64*768 + kd*64;
    for (int i = t; i < 4096; i += 320)
        A[(i&63)*65 + (i>>6)] = src[(size_t)(i>>6)*768 + (i&63)];
    __syncthreads();
    // f2-part: thread = h(0..63) x g(0..3); g handles pairs p = g*3+1..g*3+3
    if (t < 256) {
        int h = t & 63, g = t >> 6;
        int p0 = g*3 + 1;
        double aA[3] = {0,0,0}, aB[3] = {0,0,0}, acc0 = 0;
        int idx[3], stp[3];
        #pragma unroll
        for (int u = 0; u < 3; u++) { stp[u] = (p0+u)*16; idx[u] = 0; }
        #pragma unroll 4
        for (int w = 0; w < 64; w++) {
            double a = A[w*65+h];
            if (g == 0) acc0 = add2(acc0, a);
            #pragma unroll
            for (int u = 0; u < 3; u++) {
                double2 e = *(const double2*)((const char*)T2 + idx[u]);
                idx[u] = (idx[u] + stp[u]) & 1023;
                aA[u] = ffma2(a, e.x, aA[u]);
                aB[u] = ffma2(a, e.y, aB[u]);
            }
        }
        #pragma unroll
        for (int u = 0; u < 3; u++) {
            int p = p0 + u;
            float Ax = plo(aA[u]), Cx = phi(aA[u]);
            float Dx = plo(aB[u]), Bx = phi(aB[u]);
            if (p < 12) {
                B2r[p*65+h]      = Ax+Bx;  B2i[p*65+h]      = Cx-Dx;
                B2r[(24-p)*65+h] = Ax-Bx;  B2i[(24-p)*65+h] = Cx+Dx;
            } else {
                B2r[12*65+h]     = Ax-Bx;  B2i[12*65+h]     = Cx+Dx;   // kw=52
            }
        }
        if (g == 0) { B2r[h] = plo(acc0); B2i[h] = phi(acc0); }        // kw=0
    }
    __syncthreads();
    // f3-part: 312 items (kw, pp)
    if (t < 312) {
        int kw = t % 24, pp = t / 24;
        float2* o = g_X3 + (size_t)(bc*12 + kd)*576;
        if (pp < 12) {
            int p = pp + 1;
            float Ax=0, Bx=0, Cx=0, Dx=0;
            int ei = 0, es = (p*8) & 511;
            #pragma unroll 4
            for (int h = 0; h < 64; h++) {
                float ax = B2r[kw*65+h], ay = B2i[kw*65+h];
                float2 e = *(const float2*)((const char*)E + ei);
                ei = (ei + es) & 511;
                Ax = fmaf(ax, e.x, Ax); Dx = fmaf(ax, e.y, Dx);
                Cx = fmaf(ay, e.x, Cx); Bx = fmaf(ay, e.y, Bx);
            }
            if (p < 12) {
                o[p*24 + kw]      = make_float2(Ax+Bx, Cx-Dx);
                o[(24-p)*24 + kw] = make_float2(Ax-Bx, Cx+Dx);
            } else {
                o[12*24 + kw]     = make_float2(Ax-Bx, Cx+Dx);
            }
        } else {
            float r = 0, im = 0;
            #pragma unroll 4
            for (int h = 0; h < 64; h++) { r += B2r[kw*65+h]; im += B2i[kw*65+h]; }
            o[kw] = make_float2(r, im);
        }
    }
}

// MIX. grid 576, 256 thr, dyn smem 110592 (unchanged)
__global__ void __launch_bounds__(256) k_mix(
        const float* __restrict__ w1re, const float* __restrict__ w1im,
        const float* __restrict__ w2re, const float* __restrict__ w2im,
        const float* __restrict__ w3re, const float* __restrict__ w3im,
        const float* __restrict__ w4re, const float* __restrict__ w4im) {
    extern __shared__ float sm[];
    float*  Wre = sm;
    float*  Wim = sm + 12288;
    float2* X3s = (float2*)(sm + 24576);
    const float* wres[4] = {w1re, w2re, w3re, w4re};
    const float* wims[4] = {w1im, w2im, w3im, w4im};
    int t = threadIdx.x;
    int q = blockIdx.x / 144, mm = blockIdx.x % 144;
    int m1 = mm / 12, m2 = mm % 12;
    int mhw = (m1 + (q&1)*12)*24 + m2 + ((q>>1)&1)*12;
    const float* wre = wres[q];
    const float* wim = wims[q];
    int woff = m1*144 + m2*12;
    for (int idx = t; idx < 3072; idx += 256) {
        int io = idx / 3, r3 = idx - io*3;
        size_t g = (size_t)io*1728 + woff + r3*4;
        float4 vr = *(const float4*)(wre + g);
        float4 vi = *(const float4*)(wim + g);
        int sl = ((io>>5)*12 + r3*4)*32 + (io&31);
        Wre[sl] = vr.x; Wre[sl+32] = vr.y; Wre[sl+64] = vr.z; Wre[sl+96] = vr.w;
        Wim[sl] = vi.x; Wim[sl+32] = vi.y; Wim[sl+64] = vi.z; Wim[sl+96] = vi.w;
    }
    for (int idx = t; idx < 1536; idx += 256)
        X3s[idx] = g_X3[(size_t)idx*576 + mhw];
    __syncthreads();
    int o = t & 31, b = (t >> 5) & 3, kdh = t >> 7;
    float2 acc[6];
    #pragma unroll
    for (int u = 0; u < 6; u++) acc[u] = make_float2(0,0);
    for (int i = 0; i < 32; i++) {
        int xb = (b*32+i)*12 + kdh*6, wb = i*384 + kdh*192 + o;
        #pragma unroll
        for (int u = 0; u < 6; u++) {
            float2 a = X3s[xb+u];
            float wr = Wre[wb+u*32], wi = Wim[wb+u*32];
            acc[u].x = fmaf(a.x,wr,fmaf(-a.y,wi,acc[u].x));
            acc[u].y = fmaf(a.x,wi,fmaf( a.y,wr,acc[u].y));
        }
    }
    #pragma unroll
    for (int u = 0; u < 6; u++)
        g_Y[((size_t)(b*32+o)*12 + kdh*6+u)*576 + mhw] = acc[u];
}

// I1: inverse DFT along H, paired; compact float2 twiddles. grid 1536, 256 thr
__global__ void __launch_bounds__(256) k_i1() {
    __shared__ double Yp[264], Ym[264];
    __shared__ double Y0[24], Y52a[24], Y52b[24];
    __shared__ float2 E[64];
    int t = threadIdx.x;
    initE(E, t, 256);
    int bo = blockIdx.x / 12, kd = blockIdx.x % 12;
    const float2* Yr = g_Y + (size_t)(bo*12+kd)*576;
    for (int i = t; i < 312; i += 256) {
        if (i < 264) {
            int p = i/24 + 1, kw = i % 24;
            float2 z1 = Yr[p*24 + kw], z2 = Yr[(24-p)*24 + kw];
            Yp[i] = pk(z1.x + z2.x, z1.y + z2.y);
            Ym[i] = pk(z2.y - z1.y, z1.x - z2.x);
        } else if (i < 288) {
            int kw = i - 264;
            float2 z = Yr[kw];
            Y0[kw] = pk(z.x, z.y);
        } else {
            int kw = i - 288;
            float2 z = Yr[12*24 + kw];
            Y52a[kw] = pk(z.x, z.y);
            Y52b[kw] = pk(-z.y, z.x);
        }
    }
    __syncthreads();
    int h = t & 63, kwg = t >> 6;
    int kw0 = kwg * 6;
    double acc[6];
    #pragma unroll
    for (int u = 0; u < 6; u++) acc[u] = Y0[kw0+u];
    int ei = (h*8) & 511, es = h*8;
    for (int p = 1; p <= 11; p++) {
        float2 ef = *(const float2*)((const char*)E + ei);
        ei = (ei + es) & 511;
        double ex = pk(ef.x, ef.x), ey = pk(ef.y, ef.y);
        int base = (p-1)*24 + kw0;
        #pragma unroll
        for (int u = 0; u < 6; u++) {
            acc[u] = ffma2(Yp[base+u], ex, acc[u]);
            acc[u] = ffma2(Ym[base+u], ey, acc[u]);
        }
    }
    float2 e52f = E[(52*h) & 63];
    double e52x = pk(e52f.x, e52f.x), e52y = pk(e52f.y, e52f.y);
    #pragma unroll
    for (int u = 0; u < 6; u++) {
        acc[u] = ffma2(Y52a[kw0+u], e52x, acc[u]);
        acc[u] = ffma2(Y52b[kw0+u], e52y, acc[u]);
    }
    double* o = (double*)g_Z1 + ((size_t)(bo*64+h)*12 + kd)*24 + kw0;
    #pragma unroll
    for (int u = 0; u < 6; u++) o[u] = acc[u];
}

// I23: fused inverse W (paired) + real inverse D + corr. grid 8192, 256 thr
__global__ void __launch_bounds__(256) k_i23(float* __restrict__ out) {
    __shared__ double Zp[132], Zm[132];
    __shared__ double Z0[12], Z52a[12], Z52b[12];
    __shared__ __align__(16) double Zw[768];
    __shared__ float2 E[64];
    int t = threadIdx.x;
    initE(E, t, 256);
    size_t boh = blockIdx.x;
    const float2* src = g_Z1 + boh*288;
    for (int i = t; i < 144; i += 256) {
        if (i < 132) {
            int kd = i / 11, p = i % 11 + 1;
            float2 z1 = src[kd*24 + p], z2 = src[kd*24 + 24 - p];
            Zp[i] = pk(z1.x + z2.x, z1.y + z2.y);
            Zm[i] = pk(z2.y - z1.y, z1.x - z2.x);
        } else {
            int kd = i - 132;
            float2 z0 = src[kd*24];
            Z0[kd] = pk(z0.x, z0.y);
            float2 zc = src[kd*24 + 12];
            Z52a[kd] = pk(zc.x, zc.y);
            Z52b[kd] = pk(-zc.y, zc.x);
        }
    }
    __syncthreads();
    {
        int w = t & 63, kdg = t >> 6;
        double acc[3];
        #pragma unroll
        for (int u = 0; u < 3; u++) acc[u] = Z0[kdg*3+u];
        int ei = (w*8) & 511, es = w*8;
        for (int p = 1; p <= 11; p++) {
            float2 ef = *(const float2*)((const char*)E + ei);
            ei = (ei + es) & 511;
            double ex = pk(ef.x, ef.x), ey = pk(ef.y, ef.y);
            #pragma unroll
            for (int u = 0; u < 3; u++) {
                int idx = (kdg*3+u)*11 + p - 1;
                acc[u] = ffma2(Zp[idx], ex, acc[u]);
                acc[u] = ffma2(Zm[idx], ey, acc[u]);
            }
        }
        float2 e52f = E[(52*w) & 63];
        double e52x = pk(e52f.x, e52f.x), e52y = pk(e52f.y, e52f.y);
        #pragma unroll
        for (int u = 0; u < 3; u++) {
            acc[u] = ffma2(Z52a[kdg*3+u], e52x, acc[u]);
            acc[u] = ffma2(Z52b[kdg*3+u], e52y, acc[u]);
        }
        #pragma unroll
        for (int u = 0; u < 3; u++) Zw[w*12 + kdg*3+u] = acc[u];
    }
    __syncthreads();
    int d = t & 63, wg = t >> 6;
    int b = blockIdx.x >> 11, o = (blockIdx.x >> 6) & 31;
    float cv = g_CORR[(b*32+o)*64 + d];
    const float SC = 1.0f/262144.0f;
    double F2[12];
    F2[0] = pk(1.f, 0.f);
    #pragma unroll
    for (int k = 1; k <= 11; k++) {
        float2 e = E[(k*d)&63];
        F2[k] = pk(2.f*e.x, -2.f*e.y);
    }
    float* orow = out + boh*4096;
    #pragma unroll 2
    for (int j = 0; j < 16; j++) {
        int w = wg*16 + j;
        const double2* z2 = (const double2*)&Zw[w*12];
        double acc = 0;
        #pragma unroll
        for (int m = 0; m < 6; m++) {
            double2 zz = z2[m];
            acc = ffma2(zz.x, F2[2*m], acc);
            acc = ffma2(zz.y, F2[2*m+1], acc);
        }
        orow[w*64 + d] = fmaf(SC, plo(acc) + phi(acc), cv);
    }
}

// CK1: per-segment partials. grid 256, 256 thr (unchanged)
__global__ void k_ck1(const float* __restrict__ x) {
    __shared__ float2 E[64];
    int t = threadIdx.x;
    initE(E, t, 256);
    __syncthreads();
    int bid = blockIdx.x;
    int b = bid >> 6, dc = (bid >> 3) & 7, s = bid & 7;
    int c = t >> 3, d = dc*8 + (t & 7);
    float ts = -1.0f + (2.0f/7.0f)*s;
    float p1 = ts, p2 = 2.0f*ts*ts - 1.0f;
    float ar[9], ai[9];
    #pragma unroll
    for (int i = 0; i < 9; i++) { ar[i]=0; ai[i]=0; }
    const float* base = x + ((size_t)(b*32+c)*64 + s)*4096 + d;
    for (int w = 0; w < 64; w++) {
        float xv = base[w*64];
        float2 e1 = E[w], e2 = E[(2*w)&63];
        float m0 = xv, m1 = xv*p1, m2 = xv*p2;
        ar[0] += m0;
        ar[1]=fmaf(m0,e1.x,ar[1]); ai[1]=fmaf(-m0,e1.y,ai[1]);
        ar[2]=fmaf(m0,e2.x,ar[2]); ai[2]=fmaf(-m0,e2.y,ai[2]);
        ar[3] += m1;
        ar[4]=fmaf(m1,e1.x,ar[4]); ai[4]=fmaf(-m1,e1.y,ai[4]);
        ar[5]=fmaf(m1,e2.x,ar[5]); ai[5]=fmaf(-m1,e2.y,ai[5]);
        ar[6] += m2;
        ar[7]=fmaf(m2,e1.x,ar[7]); ai[7]=fmaf(-m2,e1.y,ai[7]);
        ar[8]=fmaf(m2,e2.x,ar[8]); ai[8]=fmaf(-m2,e2.y,ai[8]);
    }
    float* dst = &g_CFTP[s][b*64+d][c*18];
    #pragma unroll
    for (int i = 0; i < 9; i++) {
        dst[i*2]   = ar[i]*0.125f;
        dst[i*2+1] = ai[i]*0.125f;
    }
}

// CK2: sum partials + MLP. grid 256, 128 thr (unchanged)
__global__ void k_ck2(const float* __restrict__ W1, const float* __restrict__ b1,
                      const float* __restrict__ W2, const float* __restrict__ b2,
                      const float* __restrict__ corr_scale) {
    __shared__ float fl[576];
    __shared__ float hb[128];
    int n = blockIdx.x, t = threadIdx.x;
    for (int i = t; i < 576; i += 128) {
        float v = 0;
        #pragma unroll
        for (int s = 0; s < 8; s++) v += g_CFTP[s][n][i];
        fl[i] = v;
    }
    __syncthreads();
    float acc = b1[t];
    #pragma unroll 4
    for (int k = 0; k < 576; k++)
        acc = fmaf(fl[k], W1[(size_t)k*128 + t], acc);
    hb[t] = 0.5f*acc*(1.0f + erff(acc*0.70710678118654752f));
    __syncthreads();
    if (t < 32) {
        float a2 = b2[t];
        #pragma unroll 4
        for (int k = 0; k < 128; k++)
            a2 = fmaf(hb[k], W2[k*32 + t], a2);
        g_CORR[((n>>6)*32 + t)*64 + (n&63)] = a2*corr_scale[0];
    }
}

extern "C" void kernel_launch(void* const* d_in, const int* in_sizes, int n_in,
                              void* d_out, int out_size) {
    const float* x    = (const float*)d_in[0];
    const float* w1re = (const float*)d_in[1];
    const float* w1im = (const float*)d_in[2];
    const float* w2re = (const float*)d_in[3];
    const float* w2im = (const float*)d_in[4];
    const float* w3re = (const float*)d_in[5];
    const float* w3im = (const float*)d_in[6];
    const float* w4re = (const float*)d_in[7];
    const float* w4im = (const float*)d_in[8];
    const float* W1   = (const float*)d_in[9];
    const float* b1   = (const float*)d_in[10];
    const float* W2   = (const float*)d_in[11];
    const float* b2   = (const float*)d_in[12];
    const float* cs   = (const float*)d_in[13];
    float* out = (float*)d_out;

    static int smem_set = 0;
    const int mix_smem = 110592;
    if (!smem_set) {
        cudaFuncSetAttribute(k_mix, cudaFuncAttributeMaxDynamicSharedMemorySize, mix_smem);
        smem_set = 1;
    }

    k_ck1<<<256, 256>>>(x);
    k_ck2<<<256, 128>>>(W1, b1, W2, b2, cs);

    k_f1<<<4096, 128>>>(x);
    k_f23<<<1536, 320>>>();
    k_mix<<<576, 256, mix_smem>>>(w1re, w1im, w2re, w2im, w3re, w3im, w4re, w4im);
    k_i1<<<1536, 256>>>();
    k_i23<<<8192, 256>>>(out);
}